// round 11
// baseline (speedup 1.0000x reference)
#include <cuda_runtime.h>
#include <math.h>
#include <float.h>

#define G   1024
#define KNN 8
#define LD  64          // k-major leading dim for T/F tiles

typedef unsigned long long u64;

// diff weights (Wtop - Wbot), precomputed once
__device__ float g_Wd1[128*128];
__device__ float g_Wd2[128*128];

// ---- smem layout (float offsets) ----
#define OFF_T    0                  // 128*64  trk feats k-major; later V2 row-major ld128
#define OFF_F    8192               // 128*64  f1 feats k-major
#define OFF_W    16384              // 4096    weight chunk buffer
#define OFF_SC   20480              // 4160    scores 64x65; also init x/W; V1 (16x130); colpart (128*16)
#define OFF_S    24640              // 2048    sv feats k-major ld16; later head scratch
#define OFF_N    26688              // 64      sq norms
#define OFF_IDX  26752              // 512     idxs (int)
#define SMEM_FLOATS 27264

__device__ __forceinline__ float eluf(float x) { return x > 0.f ? x : expm1f(x); }

__device__ __forceinline__ u64 splat2(float a) {
    u64 r; asm("mov.b64 %0, {%1, %1};" : "=l"(r) : "f"(a)); return r;
}
__device__ __forceinline__ void ffma2(u64& c, u64 a, u64 b) {
    asm("fma.rn.f32x2 %0, %1, %2, %0;" : "+l"(c) : "l"(a), "l"(b));
}
__device__ __forceinline__ float2 unpack2(u64 v) {
    float2 f; asm("mov.b64 {%0, %1}, %2;" : "=f"(f.x), "=f"(f.y) : "l"(v)); return f;
}

// ---- 64-row GEMM pass: acc[4][4] += Hs(64x128 k-major) @ Wg(128x128) ----
// thread: tx=tid&15 -> col u64s {tx, tx+16, tx+32, tx+48} (cols 2tx+32j);
//         ty4=(tid>>4)*4 -> rows ty4..ty4+3. Weight streamed in 4 chunks,
//         reg double-buffered, single smem buffer.
__device__ __forceinline__ void gemm64_pass(const float* __restrict__ Hs, float* Wb,
        const float* __restrict__ Wg, u64 acc[4][4], int tid, int tx, int ty4)
{
    float4 wr[4];
    #pragma unroll
    for (int e = 0; e < 4; e++) wr[e] = ((const float4*)Wg)[tid + e*256];
    #pragma unroll
    for (int e = 0; e < 4; e++) ((float4*)Wb)[tid + e*256] = wr[e];
    __syncthreads();
    #pragma unroll
    for (int kc = 0; kc < 4; kc++) {
        if (kc < 3) {
            #pragma unroll
            for (int e = 0; e < 4; e++) wr[e] = ((const float4*)Wg)[(kc+1)*1024 + tid + e*256];
        }
        const float* Hc = Hs + kc * 32 * LD;
        #pragma unroll 4
        for (int kk = 0; kk < 32; kk++) {
            float4 a = *(const float4*)&Hc[kk*LD + ty4];
            const u64* br = (const u64*)&Wb[kk*128];
            u64 b0 = br[tx], b1 = br[tx+16], b2 = br[tx+32], b3 = br[tx+48];
            u64 s;
            s=splat2(a.x); ffma2(acc[0][0],s,b0); ffma2(acc[0][1],s,b1); ffma2(acc[0][2],s,b2); ffma2(acc[0][3],s,b3);
            s=splat2(a.y); ffma2(acc[1][0],s,b0); ffma2(acc[1][1],s,b1); ffma2(acc[1][2],s,b2); ffma2(acc[1][3],s,b3);
            s=splat2(a.z); ffma2(acc[2][0],s,b0); ffma2(acc[2][1],s,b1); ffma2(acc[2][2],s,b2); ffma2(acc[2][3],s,b3);
            s=splat2(a.w); ffma2(acc[3][0],s,b0); ffma2(acc[3][1],s,b1); ffma2(acc[3][2],s,b2); ffma2(acc[3][3],s,b3);
        }
        __syncthreads();
        if (kc < 3) {
            #pragma unroll
            for (int e = 0; e < 4; e++) ((float4*)Wb)[tid + e*256] = wr[e];
            __syncthreads();
        }
    }
}

// ---- 16-row GEMM pass: acc[4] += Ss(16x128 k-major ld16) @ Wg ----
// thread: r16=tid>>4 row, c8=(tid&15)*8 cols c8..c8+7.
__device__ __forceinline__ void gemm16_pass(const float* __restrict__ Ss, float* Wb,
        const float* __restrict__ Wg, u64 acc[4], int tid, int r16, int c8)
{
    float4 wr[4];
    #pragma unroll
    for (int e = 0; e < 4; e++) wr[e] = ((const float4*)Wg)[tid + e*256];
    #pragma unroll
    for (int e = 0; e < 4; e++) ((float4*)Wb)[tid + e*256] = wr[e];
    __syncthreads();
    #pragma unroll
    for (int kc = 0; kc < 4; kc++) {
        if (kc < 3) {
            #pragma unroll
            for (int e = 0; e < 4; e++) wr[e] = ((const float4*)Wg)[(kc+1)*1024 + tid + e*256];
        }
        #pragma unroll 4
        for (int kk = 0; kk < 32; kk++) {
            u64 s = splat2(Ss[(kc*32+kk)*16 + r16]);
            const u64* br = (const u64*)&Wb[kk*128 + c8];
            ffma2(acc[0], s, br[0]); ffma2(acc[1], s, br[1]);
            ffma2(acc[2], s, br[2]); ffma2(acc[3], s, br[3]);
        }
        __syncthreads();
        if (kc < 3) {
            #pragma unroll
            for (int e = 0; e < 4; e++) ((float4*)Wb)[tid + e*256] = wr[e];
            __syncthreads();
        }
    }
}

// ---------------- diff-weight precompute ----------------
__global__ __launch_bounds__(256)
void diff_kernel(const float* __restrict__ Wc1, const float* __restrict__ Wc2,
                 float* __restrict__ D1, float* __restrict__ D2)
{
    int i = blockIdx.x * 256 + threadIdx.x;
    D1[i] = Wc1[i] - Wc1[i + 16384];
    D2[i] = Wc2[i] - Wc2[i + 16384];
}

// =====================================================================
// Megakernel: one block per graph, everything in SMEM.
// =====================================================================
__global__ __launch_bounds__(256, 2)
void mega_kernel(const float* __restrict__ x_sv,  const float* __restrict__ x_trk,
                 const float* __restrict__ Wsv1, const float* __restrict__ bsv1,
                 const float* __restrict__ Wsv2, const float* __restrict__ bsv2,
                 const float* __restrict__ Wtk1, const float* __restrict__ btk1,
                 const float* __restrict__ Wtk2, const float* __restrict__ btk2,
                 const float* __restrict__ Wd1,  const float* __restrict__ bc1,
                 const float* __restrict__ Wbot1,
                 const float* __restrict__ Wd2,  const float* __restrict__ bc2,
                 const float* __restrict__ Wbot2,
                 const float* __restrict__ Wo1, const float* __restrict__ bo1,
                 const float* __restrict__ Wo2, const float* __restrict__ bo2,
                 const float* __restrict__ Wo3, const float* __restrict__ bo3,
                 const float* __restrict__ Wo4, const float* __restrict__ bo4,
                 float* __restrict__ out, int out_size)
{
    extern __shared__ float sm[];
    float* Ts = sm + OFF_T;
    float* Fs = sm + OFF_F;
    float* Wb = sm + OFF_W;
    float* sc = sm + OFF_SC;
    float* Ss = sm + OFF_S;
    float* sn2 = sm + OFF_N;
    int*  idxs = (int*)(sm + OFF_IDX);

    const int g    = blockIdx.x;
    const int tid  = threadIdx.x;
    const int lane = tid & 31, w = tid >> 5;
    const int tx   = tid & 15, ty4 = (tid >> 4) * 4;
    const int r16  = tid >> 4, c8 = tx * 8;

    // ---- P0: stage inputs + layer-1 weights into sc region ----
    float* XT  = sc;          // 512
    float* XS  = sc + 512;    // 32
    float* W1T = sc + 544;    // 1024
    float* B1T = sc + 1568;   // 128
    float* W1S = sc + 1696;   // 256
    float* B1S = sc + 1952;   // 128
    for (int t = tid; t < 512; t += 256) XT[t] = x_trk[(size_t)g*512 + t];
    if (tid < 32)  XS[tid]  = x_sv[(size_t)g*32 + tid];
    for (int t = tid; t < 1024; t += 256) W1T[t] = Wtk1[t];
    if (tid < 128) B1T[tid] = btk1[tid];
    if (tid < 256) W1S[tid] = Wsv1[tid];
    if (tid < 128) B1S[tid] = bsv1[tid];
    __syncthreads();

    // ---- P1: layer 1 -> T (k-major), S (k-major ld16) ----
    {
        int r = tid >> 2, cg = (tid & 3) * 32;
        float xr[8];
        #pragma unroll
        for (int d = 0; d < 8; d++) xr[d] = XT[r*8 + d];
        #pragma unroll 4
        for (int cc = 0; cc < 32; cc++) {
            int c = cg + cc;
            float a = B1T[c];
            #pragma unroll
            for (int d = 0; d < 8; d++) a = fmaf(xr[d], W1T[d*128 + c], a);
            Ts[c*LD + r] = eluf(a);
        }
        float x0 = XS[r16*2], x1 = XS[r16*2 + 1];
        #pragma unroll
        for (int cc = 0; cc < 8; cc++) {
            int c = c8 + cc;
            float a = B1S[c] + x0 * W1S[c] + x1 * W1S[128 + c];
            Ss[c*16 + r16] = eluf(a);
        }
    }
    // (gemm pass's first sync orders layer-1 writes before reads)

    // ---- P2: layer 2 for trk and sv ----
    u64 accA[4][4];
    #pragma unroll
    for (int i = 0; i < 4; i++) { accA[i][0]=0; accA[i][1]=0; accA[i][2]=0; accA[i][3]=0; }
    gemm64_pass(Ts, Wb, Wtk2, accA, tid, tx, ty4);
    u64 acc4[4] = {0ull, 0ull, 0ull, 0ull};
    gemm16_pass(Ss, Wb, Wsv2, acc4, tid, r16, c8);
    // both passes end synced -> all T/S reads done; write back relu feats
    {
        #pragma unroll
        for (int j = 0; j < 4; j++) {
            float2 bv = *(const float2*)&btk2[2*tx + 32*j];
            #pragma unroll
            for (int ii = 0; ii < 4; ii++) {
                float2 p = unpack2(accA[ii][j]);
                Ts[(2*tx + 32*j)    *LD + ty4 + ii] = fmaxf(p.x + bv.x, 0.f);
                Ts[(2*tx + 32*j + 1)*LD + ty4 + ii] = fmaxf(p.y + bv.y, 0.f);
            }
        }
        #pragma unroll
        for (int m = 0; m < 4; m++) {
            float2 p = unpack2(acc4[m]);
            int c = c8 + 2*m;
            Ss[c*16 + r16]     = fmaxf(p.x + bsv2[c],   0.f);
            Ss[(c+1)*16 + r16] = fmaxf(p.y + bsv2[c+1], 0.f);
        }
    }

    // ---- P3: U1 = T @ Wd1 (held in registers) ----
    u64 accU[4][4];
    #pragma unroll
    for (int i = 0; i < 4; i++) { accU[i][0]=0; accU[i][1]=0; accU[i][2]=0; accU[i][3]=0; }
    gemm64_pass(Ts, Wb, Wd1, accU, tid, tx, ty4);

    // ---- P4: sv squared norms ----
    {
        int j = tid >> 4, kq = tid & 15;
        float s = 0.f;
        #pragma unroll
        for (int t = 0; t < 8; t++) { float v = Ss[(kq*8 + t)*16 + j]; s += v*v; }
        s += __shfl_xor_sync(~0u, s, 8);
        s += __shfl_xor_sync(~0u, s, 4);
        s += __shfl_xor_sync(~0u, s, 2);
        s += __shfl_xor_sync(~0u, s, 1);
        if ((lane & 15) == 0) sn2[j] = s;
    }
    __syncthreads();

    // ---- P5: scores1 = ||s_j||^2 - 2 dot(T_i, S_j) ----
    {
        u64 a0 = 0ull, a1 = 0ull;
        int j0 = 2*w;
        #pragma unroll 8
        for (int k = 0; k < 128; k++) {
            u64 av = *(const u64*)&Ts[k*LD + 2*lane];
            ffma2(a0, av, splat2(Ss[k*16 + j0]));
            ffma2(a1, av, splat2(Ss[k*16 + j0 + 1]));
        }
        float2 p = unpack2(a0);
        sc[(2*lane)  *65 + j0] = sn2[j0] - 2.f*p.x;
        sc[(2*lane+1)*65 + j0] = sn2[j0] - 2.f*p.y;
        p = unpack2(a1);
        sc[(2*lane)  *65 + j0+1] = sn2[j0+1] - 2.f*p.x;
        sc[(2*lane+1)*65 + j0+1] = sn2[j0+1] - 2.f*p.y;
    }
    __syncthreads();

    // ---- P6: topk1 (16 candidates, tie -> lowest idx) ----
    #pragma unroll
    for (int q = 0; q < 8; q++) {
        int row = w*8 + q;
        float mv = (lane < 16) ? sc[row*65 + lane] : FLT_MAX;
        #pragma unroll
        for (int n = 0; n < KNN; n++) {
            float cv = mv; int ci = lane;
            #pragma unroll
            for (int off = 16; off > 0; off >>= 1) {
                float ov = __shfl_xor_sync(~0u, cv, off);
                int   oi = __shfl_xor_sync(~0u, ci, off);
                if (ov < cv || (ov == cv && oi < ci)) { cv = ov; ci = oi; }
            }
            if (lane == 0) idxs[row*8 + n] = ci;
            if (lane == ci) mv = FLT_MAX;
        }
    }
    // (gemm16 pass's first sync orders idxs writes / sc reads)

    // ---- P7: V1 = S @ Wbot1 -> sc region (ld 130) ----
    u64 accV1[4] = {0ull, 0ull, 0ull, 0ull};
    gemm16_pass(Ss, Wb, Wbot1, accV1, tid, r16, c8);
    float* V1 = sc;
    {
        #pragma unroll
        for (int m = 0; m < 4; m++) {
            float2 p = unpack2(accV1[m]);
            *(float2*)&V1[r16*130 + c8 + 2*m] = p;
        }
    }
    __syncthreads();

    // ---- P8: combine1 -> F = elu(U1 + bc1 + max_n V1[idx]) (k-major) ----
    {
        #pragma unroll
        for (int ii = 0; ii < 4; ii++) {
            int i = ty4 + ii;
            const int* ip_ = &idxs[i*8];
            float mx[4], my[4];
            #pragma unroll
            for (int j = 0; j < 4; j++) { mx[j] = -FLT_MAX; my[j] = -FLT_MAX; }
            #pragma unroll
            for (int n = 0; n < KNN; n++) {
                int jj = ip_[n];
                #pragma unroll
                for (int j = 0; j < 4; j++) {
                    float2 v = *(const float2*)&V1[jj*130 + 2*tx + 32*j];
                    mx[j] = fmaxf(mx[j], v.x); my[j] = fmaxf(my[j], v.y);
                }
            }
            #pragma unroll
            for (int j = 0; j < 4; j++) {
                float2 bv = *(const float2*)&bc1[2*tx + 32*j];
                float2 p = unpack2(accU[ii][j]);
                Fs[(2*tx + 32*j)    *LD + i] = eluf(p.x + bv.x + mx[j]);
                Fs[(2*tx + 32*j + 1)*LD + i] = eluf(p.y + bv.y + my[j]);
            }
        }
    }

    // ---- P9: U2 = T @ Wd2 (registers) ----
    #pragma unroll
    for (int i = 0; i < 4; i++) { accU[i][0]=0; accU[i][1]=0; accU[i][2]=0; accU[i][3]=0; }
    gemm64_pass(Ts, Wb, Wd2, accU, tid, tx, ty4);   // first sync covers F writes

    // ---- P10: f1 squared norms (64 rows) ----
    {
        int j = tid >> 2, kq = tid & 3;
        float s = 0.f;
        #pragma unroll 8
        for (int t = 0; t < 32; t++) { float v = Fs[(kq*32 + t)*LD + j]; s += v*v; }
        s += __shfl_xor_sync(~0u, s, 2);
        s += __shfl_xor_sync(~0u, s, 1);
        if ((lane & 3) == 0) sn2[j] = s;
    }
    __syncthreads();

    // ---- P11: scores2 = ||f_j||^2 - 2 dot(T_i, F_j) ----
    {
        u64 a2[8];
        #pragma unroll
        for (int i = 0; i < 8; i++) a2[i] = 0ull;
        #pragma unroll 4
        for (int k = 0; k < 128; k++) {
            float4 q0 = *(const float4*)&Ts[k*LD + w*8];
            float4 q1 = *(const float4*)&Ts[k*LD + w*8 + 4];
            u64 b = *(const u64*)&Fs[k*LD + 2*lane];
            ffma2(a2[0], splat2(q0.x), b); ffma2(a2[1], splat2(q0.y), b);
            ffma2(a2[2], splat2(q0.z), b); ffma2(a2[3], splat2(q0.w), b);
            ffma2(a2[4], splat2(q1.x), b); ffma2(a2[5], splat2(q1.y), b);
            ffma2(a2[6], splat2(q1.z), b); ffma2(a2[7], splat2(q1.w), b);
        }
        float s0 = sn2[2*lane], s1 = sn2[2*lane + 1];
        #pragma unroll
        for (int ii = 0; ii < 8; ii++) {
            float2 p = unpack2(a2[ii]);
            sc[(w*8 + ii)*65 + 2*lane]     = s0 - 2.f*p.x;
            sc[(w*8 + ii)*65 + 2*lane + 1] = s1 - 2.f*p.y;
        }
    }
    __syncthreads();

    // ---- P12: topk2 (64 candidates) ----
    #pragma unroll
    for (int q = 0; q < 8; q++) {
        int row = w*8 + q;
        float v0 = sc[row*65 + lane];
        float v1 = sc[row*65 + 32 + lane];
        #pragma unroll
        for (int n = 0; n < KNN; n++) {
            float cv; int ci;
            if (v1 < v0) { cv = v1; ci = lane + 32; }
            else         { cv = v0; ci = lane; }
            #pragma unroll
            for (int off = 16; off > 0; off >>= 1) {
                float ov = __shfl_xor_sync(~0u, cv, off);
                int   oi = __shfl_xor_sync(~0u, ci, off);
                if (ov < cv || (ov == cv && oi < ci)) { cv = ov; ci = oi; }
            }
            if (lane == 0) idxs[row*8 + n] = ci;
            if (ci == lane)           v0 = FLT_MAX;
            else if (ci == lane + 32) v1 = FLT_MAX;
        }
    }
    // (gemm64 pass's first sync orders idxs writes / sc & T reads)

    // ---- P13: V2 = F @ Wbot2 -> T region (row-major ld 128) ----
    u64 accV[4][4];
    #pragma unroll
    for (int i = 0; i < 4; i++) { accV[i][0]=0; accV[i][1]=0; accV[i][2]=0; accV[i][3]=0; }
    gemm64_pass(Fs, Wb, Wbot2, accV, tid, tx, ty4);
    float* V2 = Ts;   // T dead (scores2/U2 done before pass's first sync)
    {
        #pragma unroll
        for (int ii = 0; ii < 4; ii++) {
            int i = ty4 + ii;
            #pragma unroll
            for (int j = 0; j < 4; j++) {
                float2 p = unpack2(accV[ii][j]);
                *(float2*)&V2[i*128 + 2*tx + 32*j] = p;
            }
        }
    }
    __syncthreads();

    // ---- P14: combine2 + column partial sums ----
    float* colpart = sc;    // 128*16
    {
        float cs[4], cs2[4];
        #pragma unroll
        for (int j = 0; j < 4; j++) { cs[j] = 0.f; cs2[j] = 0.f; }
        #pragma unroll
        for (int ii = 0; ii < 4; ii++) {
            int i = ty4 + ii;
            const int* ip_ = &idxs[i*8];
            float mx[4], my[4];
            #pragma unroll
            for (int j = 0; j < 4; j++) { mx[j] = -FLT_MAX; my[j] = -FLT_MAX; }
            #pragma unroll
            for (int n = 0; n < KNN; n++) {
                int jj = ip_[n];
                #pragma unroll
                for (int j = 0; j < 4; j++) {
                    float2 v = *(const float2*)&V2[jj*128 + 2*tx + 32*j];
                    mx[j] = fmaxf(mx[j], v.x); my[j] = fmaxf(my[j], v.y);
                }
            }
            #pragma unroll
            for (int j = 0; j < 4; j++) {
                float2 bv = *(const float2*)&bc2[2*tx + 32*j];
                float2 p = unpack2(accU[ii][j]);
                cs[j]  += eluf(p.x + bv.x + mx[j]);
                cs2[j] += eluf(p.y + bv.y + my[j]);
            }
        }
        #pragma unroll
        for (int j = 0; j < 4; j++) {
            colpart[(2*tx + 32*j)    *16 + r16] = cs[j];
            colpart[(2*tx + 32*j + 1)*16 + r16] = cs2[j];
        }
    }
    __syncthreads();

    // ---- P15: pooled mean + head MLP ----
    float* pooled = Ss;          // S region dead
    float* h1 = Ss + 128;
    float* h2 = Ss + 192;
    float* h3 = Ss + 224;
    if (tid < 128) {
        float s = 0.f;
        #pragma unroll
        for (int t = 0; t < 16; t++) s += colpart[tid*16 + t];
        pooled[tid] = s * (1.f / 64.f);
    }
    __syncthreads();
    if (tid < 64) {
        float a = bo1[tid];
        #pragma unroll 8
        for (int d = 0; d < 128; d++) a += pooled[d] * Wo1[d*64 + tid];
        h1[tid] = eluf(a);
    }
    __syncthreads();
    if (tid < 32) {
        float a = bo2[tid];
        #pragma unroll 8
        for (int d = 0; d < 64; d++) a += h1[d] * Wo2[d*32 + tid];
        h2[tid] = eluf(a);
    }
    __syncthreads();
    if (tid < 4) {
        float a = bo3[tid];
        #pragma unroll
        for (int d = 0; d < 32; d++) a += h2[d] * Wo3[d*4 + tid];
        h3[tid] = eluf(a);
    }
    __syncthreads();
    if (tid == 0) {
        float a = bo4[0];
        #pragma unroll
        for (int d = 0; d < 4; d++) a += h3[d] * Wo4[d];
        out[g] = a;
        if (out_size >= 2 * G) out[G + g] = (float)g;
    }
}

// ---------------- launch ----------------
extern "C" void kernel_launch(void* const* d_in, const int* in_sizes, int n_in,
                              void* d_out, int out_size)
{
    const float* x_sv   = (const float*)d_in[0];
    const float* x_trk  = (const float*)d_in[1];
    const float* W_sv1  = (const float*)d_in[2];
    const float* b_sv1  = (const float*)d_in[3];
    const float* W_sv2  = (const float*)d_in[4];
    const float* b_sv2  = (const float*)d_in[5];
    const float* W_trk1 = (const float*)d_in[6];
    const float* b_trk1 = (const float*)d_in[7];
    const float* W_trk2 = (const float*)d_in[8];
    const float* b_trk2 = (const float*)d_in[9];
    const float* W_c1   = (const float*)d_in[10];
    const float* b_c1   = (const float*)d_in[11];
    const float* W_c2   = (const float*)d_in[12];
    const float* b_c2   = (const float*)d_in[13];
    const float* W_o1   = (const float*)d_in[14];
    const float* b_o1   = (const float*)d_in[15];
    const float* W_o2   = (const float*)d_in[16];
    const float* b_o2   = (const float*)d_in[17];
    const float* W_o3   = (const float*)d_in[18];
    const float* b_o3   = (const float*)d_in[19];
    const float* W_o4   = (const float*)d_in[20];
    const float* b_o4   = (const float*)d_in[21];
    float* out = (float*)d_out;

    float *p_Wd1, *p_Wd2;
    cudaGetSymbolAddress((void**)&p_Wd1, g_Wd1);
    cudaGetSymbolAddress((void**)&p_Wd2, g_Wd2);

    const int smem = SMEM_FLOATS * 4;
    (void)cudaFuncSetAttribute(mega_kernel, cudaFuncAttributeMaxDynamicSharedMemorySize, smem);

    diff_kernel<<<64, 256>>>(W_c1, W_c2, p_Wd1, p_Wd2);

    mega_kernel<<<G, 256, smem>>>(
        x_sv, x_trk,
        W_sv1, b_sv1, W_sv2, b_sv2,
        W_trk1, b_trk1, W_trk2, b_trk2,
        p_Wd1, b_c1, W_c1 + 16384,
        p_Wd2, b_c2, W_c2 + 16384,
        W_o1, b_o1, W_o2, b_o2, W_o3, b_o3, W_o4, b_o4,
        out, out_size);
}

// round 12
// speedup vs baseline: 1.0523x; 1.0523x over previous
#include <cuda_runtime.h>
#include <math.h>
#include <float.h>

#define G    1024
#define NSV  16
#define NTRK 64
#define KNN  8

typedef unsigned long long u64;

// ---------------- scratch (static device globals: no allocation) ----------------
__device__ float g_sv [G*NSV *128];
__device__ float g_trk[G*NTRK*128];
__device__ float g_U1 [G*NTRK*128];
__device__ float g_U2 [G*NTRK*128];
__device__ float g_V1 [G*NSV *128];
__device__ float g_f1 [G*NTRK*128];
__device__ float g_Wd1[128*128];   // Wc1_top - Wc1_bot
__device__ float g_Wd2[128*128];   // Wc2_top - Wc2_bot

__device__ __forceinline__ float eluf(float x) { return x > 0.f ? x : expm1f(x); }

// ---- packed f32x2 helpers ----
__device__ __forceinline__ u64 splat2(float a) {
    u64 r; asm("mov.b64 %0, {%1, %1};" : "=l"(r) : "f"(a)); return r;
}
__device__ __forceinline__ void ffma2(u64& c, u64 a, u64 b) {
    asm("fma.rn.f32x2 %0, %1, %2, %0;" : "+l"(c) : "l"(a), "l"(b));
}
__device__ __forceinline__ float2 unpack2(u64 v) {
    float2 f; asm("mov.b64 {%0, %1}, %2;" : "=f"(f.x), "=f"(f.y) : "l"(v)); return f;
}

// ---- plain 32x128 weight chunk staging (LDG->STS), 256 threads ----
__device__ __forceinline__ void stage_chunk(float* dst, const float* __restrict__ W,
                                            int kc, int tid)
{
    #pragma unroll
    for (int e = 0; e < 4; e++) {
        int i4 = tid + e * 256;               // 0..1023 float4s = 32x128 chunk
        ((float4*)dst)[i4] = ((const float4*)W)[kc * 1024 + i4];
    }
}

// ---- GEMM core over one 32-k chunk, 256 threads, 8x8 microtile ----
// Hs: [k][r] ld 132; Ws: [k][c] ld 128.
__device__ __forceinline__ void zero_acc8(u64 acc[8][4]) {
    #pragma unroll
    for (int i = 0; i < 8; i++)
        #pragma unroll
        for (int j = 0; j < 4; j++) acc[i][j] = 0ull;
}
__device__ __forceinline__ void gemm_chunk(const float* __restrict__ Hs,
                                           const float* __restrict__ Ws,
                                           u64 acc[8][4], int tx, int ty)
{
    #pragma unroll 4
    for (int kk = 0; kk < 32; kk++) {
        const float* arow = &Hs[kk * 132 + ty * 8];
        float4 a0 = *(const float4*)arow;
        float4 a1 = *(const float4*)(arow + 4);
        const u64* br = (const u64*)&Ws[kk * 128];
        u64 b0 = br[tx], b1 = br[tx + 16], b2 = br[tx + 32], b3 = br[tx + 48];
        u64 s;
        s = splat2(a0.x); ffma2(acc[0][0],s,b0); ffma2(acc[0][1],s,b1); ffma2(acc[0][2],s,b2); ffma2(acc[0][3],s,b3);
        s = splat2(a0.y); ffma2(acc[1][0],s,b0); ffma2(acc[1][1],s,b1); ffma2(acc[1][2],s,b2); ffma2(acc[1][3],s,b3);
        s = splat2(a0.z); ffma2(acc[2][0],s,b0); ffma2(acc[2][1],s,b1); ffma2(acc[2][2],s,b2); ffma2(acc[2][3],s,b3);
        s = splat2(a0.w); ffma2(acc[3][0],s,b0); ffma2(acc[3][1],s,b1); ffma2(acc[3][2],s,b2); ffma2(acc[3][3],s,b3);
        s = splat2(a1.x); ffma2(acc[4][0],s,b0); ffma2(acc[4][1],s,b1); ffma2(acc[4][2],s,b2); ffma2(acc[4][3],s,b3);
        s = splat2(a1.y); ffma2(acc[5][0],s,b0); ffma2(acc[5][1],s,b1); ffma2(acc[5][2],s,b2); ffma2(acc[5][3],s,b3);
        s = splat2(a1.z); ffma2(acc[6][0],s,b0); ffma2(acc[6][1],s,b1); ffma2(acc[6][2],s,b2); ffma2(acc[6][3],s,b3);
        s = splat2(a1.w); ffma2(acc[7][0],s,b0); ffma2(acc[7][1],s,b1); ffma2(acc[7][2],s,b2); ffma2(acc[7][3],s,b3);
    }
}
// full 128-k pass with double-buffered weight streaming (plain copy)
__device__ __forceinline__ void gemm_pass(const float* __restrict__ Hs, float* Wb,
                                          const float* __restrict__ W,
                                          u64 acc[8][4], int tid, int tx, int ty)
{
    stage_chunk(Wb, W, 0, tid);
    __syncthreads();
    #pragma unroll
    for (int kc = 0; kc < 4; kc++) {
        if (kc < 3) stage_chunk(Wb + ((kc + 1) & 1) * 4096, W, kc + 1, tid);
        gemm_chunk(Hs + kc * 32 * 132, Wb + (kc & 1) * 4096, acc, tx, ty);
        __syncthreads();
    }
}
__device__ __forceinline__ void store256(const u64 acc[8][4], float* __restrict__ C,
                                         size_t row0, int tx, int ty,
                                         const float* __restrict__ bias)
{
    float2 bv[4] = {{0,0},{0,0},{0,0},{0,0}};
    if (bias) {
        #pragma unroll
        for (int j = 0; j < 4; j++) bv[j] = *(const float2*)&bias[tx * 2 + j * 32];
    }
    #pragma unroll
    for (int ii = 0; ii < 8; ii++) {
        size_t r = row0 + ty * 8 + ii;
        #pragma unroll
        for (int j = 0; j < 4; j++) {
            float2 p = unpack2(acc[ii][j]);
            p.x += bv[j].x; p.y += bv[j].y;
            *(float2*)&C[r * 128 + tx * 2 + j * 32] = p;
        }
    }
}

// ---------------- diff-weight precompute ----------------
__global__ __launch_bounds__(256)
void diff_kernel(const float* __restrict__ Wc1, const float* __restrict__ Wc2,
                 float* __restrict__ D1, float* __restrict__ D2)
{
    int i = blockIdx.x * 256 + threadIdx.x;   // 16384 elements
    D1[i] = Wc1[i] - Wc1[i + 16384];
    D2[i] = Wc2[i] - Wc2[i + 16384];
}

// =====================================================================
// Node kernels: layer1 -> Hs; pass1 = relu(Hs@W2+b2) -> Yf + Hs;
// then NPASS-1 more weight-streamed GEMM passes (plain weights).
// 256 threads, 128-row tile, 8x8 microtile, 2 blocks/SM.
// =====================================================================
template<int IN, int NPASS>
__global__ __launch_bounds__(256, 2)
void node_kernel(const float* __restrict__ X,
                 const float* __restrict__ W1, const float* __restrict__ b1,
                 const float* __restrict__ W2, const float* __restrict__ b2,
                 const float* __restrict__ Wp1, const float* __restrict__ bc1,
                 const float* __restrict__ Wp2, const float* __restrict__ bc2,
                 float* __restrict__ Yf, float* __restrict__ Y1, float* __restrict__ Y2)
{
    extern __shared__ float sm[];
    float* Hs  = sm;                    // 128*132 = 16896
    float* Wb  = Hs + 16896;            // 2*4096
    float* Xin = Wb + 8192;             // 128*IN
    float* W1s = Xin + 128 * IN;        // IN*128
    float* b1s = W1s + IN * 128;        // 128
    const int tid = threadIdx.x;
    const int tx = tid & 15, ty = tid >> 4;
    const size_t row0 = (size_t)blockIdx.x * 128;

    for (int t = tid; t < 128 * IN; t += 256) Xin[t] = X[row0 * IN + t];
    for (int t = tid; t < IN * 128; t += 256) W1s[t] = W1[t];
    if (tid < 128) b1s[tid] = b1[tid];
    __syncthreads();

    // layer 1 -> Hs transposed [c][r]
    {
        int r = tid >> 1, ch = (tid & 1) * 64;
        float xr[IN];
        #pragma unroll
        for (int d = 0; d < IN; d++) xr[d] = Xin[r * IN + d];
        #pragma unroll 4
        for (int cc = 0; cc < 64; cc++) {
            int c = ch + cc;
            float a = b1s[c];
            #pragma unroll
            for (int d = 0; d < IN; d++) a = fmaf(xr[d], W1s[d * 128 + c], a);
            Hs[c * 132 + r] = eluf(a);
        }
    }
    // (gemm_pass's initial stage+sync orders Hs writes before reads)

    u64 acc[8][4];
    zero_acc8(acc);
    gemm_pass(Hs, Wb, W2, acc, tid, tx, ty);

    // feats = relu(acc + b2) -> Yf and Hs (transposed, in place)
    {
        float2 bv[4];
        #pragma unroll
        for (int j = 0; j < 4; j++) bv[j] = *(const float2*)&b2[tx * 2 + j * 32];
        #pragma unroll
        for (int ii = 0; ii < 8; ii++) {
            int rr = ty * 8 + ii;
            #pragma unroll
            for (int j = 0; j < 4; j++) {
                float2 p = unpack2(acc[ii][j]);
                float va = fmaxf(p.x + bv[j].x, 0.f);
                float vb = fmaxf(p.y + bv[j].y, 0.f);
                int c = tx * 2 + j * 32;
                float2 o = {va, vb};
                *(float2*)&Yf[(row0 + rr) * 128 + c] = o;
                Hs[c * 132 + rr]       = va;
                Hs[(c + 1) * 132 + rr] = vb;
            }
        }
    }
    __syncthreads();

    zero_acc8(acc);
    gemm_pass(Hs, Wb, Wp1, acc, tid, tx, ty);
    store256(acc, Y1, row0, tx, ty, (NPASS == 3) ? bc1 : nullptr);

    if (NPASS == 3) {
        zero_acc8(acc);
        gemm_pass(Hs, Wb, Wp2, acc, tid, tx, ty);
        store256(acc, Y2, row0, tx, ty, bc2);
    }
}

// =====================================================================
// conv1: kNN(trk -> 16 SVs) + gather-max + ELU -> f1.
// 256 threads/graph, 4 blocks/SM (56KB smem, <=64 regs).
// =====================================================================
__global__ __launch_bounds__(256, 4)
void conv1_kernel(const float* __restrict__ trkF, const float* __restrict__ svF,
                  const float* __restrict__ U,    const float* __restrict__ V,
                  float* __restrict__ f1out)
{
    extern __shared__ float sm[];
    float* dsh = sm;                    // 64*130
    float* ssh = dsh + 64 * 130;        // 16*130
    float* vsh = ssh + 16 * 130;        // 16*130
    float* sc  = vsh + 16 * 130;        // 64*17
    float* sn2 = sc + 64 * 17;          // 16
    int*  idxs = (int*)(sn2 + 16);      // 64*8

    const int g   = blockIdx.x;
    const int tid = threadIdx.x;
    const int wid = tid >> 5, lane = tid & 31;
    const float* dg = trkF + (size_t)g * 64 * 128;
    const float* sg = svF  + (size_t)g * 16 * 128;
    const float* Vg = V    + (size_t)g * 16 * 128;
    const float* Ug = U    + (size_t)g * 64 * 128;

    for (int t = tid; t < 64 * 128; t += 256)
        dsh[(t >> 7) * 130 + (t & 127)] = dg[t];
    for (int t = tid; t < 16 * 128; t += 256) {
        int r = t >> 7, c = t & 127;
        ssh[r * 130 + c] = sg[t];
        vsh[r * 130 + c] = Vg[t];
    }
    __syncthreads();

    // src squared norms: 8 warps, 2 rows each
    #pragma unroll
    for (int q = 0; q < 2; q++) {
        int row = wid * 2 + q;
        const float* rp = &ssh[row * 130];
        float e0 = rp[lane], e1 = rp[32 + lane], e2 = rp[64 + lane], e3 = rp[96 + lane];
        float s = e0*e0 + e1*e1 + e2*e2 + e3*e3;
        #pragma unroll
        for (int off = 16; off > 0; off >>= 1) s += __shfl_xor_sync(~0u, s, off);
        if (lane == 0) sn2[row] = s;
    }
    __syncthreads();

    // scores: i = tid>>2 (64 rows), jj = tid&3 -> j = jj + 4m
    {
        int i = tid >> 2, jj = tid & 3;
        u64 a[4] = {0ull, 0ull, 0ull, 0ull};
        #pragma unroll 8
        for (int kk = 0; kk < 64; kk++) {
            u64 av = *(const u64*)&dsh[i * 130 + kk * 2];
            #pragma unroll
            for (int m = 0; m < 4; m++) {
                u64 bv = *(const u64*)&ssh[(jj + 4 * m) * 130 + kk * 2];
                ffma2(a[m], av, bv);
            }
        }
        #pragma unroll
        for (int m = 0; m < 4; m++) {
            float2 p = unpack2(a[m]);
            int j = jj + 4 * m;
            sc[i * 17 + j] = sn2[j] - 2.f * (p.x + p.y);
        }
    }
    __syncthreads();

    // warp-parallel top-8 (tie -> lowest index): warp w rows 8w..8w+7
    #pragma unroll
    for (int q = 0; q < 8; q++) {
        int row = wid * 8 + q;
        float mv = (lane < 16) ? sc[row * 17 + lane] : FLT_MAX;
        #pragma unroll
        for (int n = 0; n < KNN; n++) {
            float cv = mv; int ci = lane;
            #pragma unroll
            for (int off = 16; off > 0; off >>= 1) {
                float ov = __shfl_xor_sync(~0u, cv, off);
                int   oi = __shfl_xor_sync(~0u, ci, off);
                if (ov < cv || (ov == cv && oi < ci)) { cv = ov; ci = oi; }
            }
            if (lane == 0) idxs[row * 8 + n] = ci;
            if (lane == ci) mv = FLT_MAX;
        }
    }
    __syncthreads();

    // f1 = elu(U(+bias folded) + max_n V[idx])
    {
        int c = tid & 127, ih = tid >> 7;   // 2 row-groups
        for (int i0 = 0; i0 < 64; i0 += 2) {
            int i = i0 + ih;
            const int* ip = &idxs[i * 8];
            float vmax = -FLT_MAX;
            #pragma unroll
            for (int n = 0; n < KNN; n++) vmax = fmaxf(vmax, vsh[ip[n] * 130 + c]);
            f1out[((size_t)g * 64 + i) * 128 + c] = eluf(Ug[i * 128 + c] + vmax);
        }
    }
}

// =====================================================================
// conv2 (FUSED): scores + topk + V2 = f1 @ Wbot2 (in-block GEMM from
// the resident f1 tile) + combine + mean pool + head.
// 512 threads/graph, regs capped for 2 blocks/SM. V2 never touches DRAM.
// =====================================================================
__global__ __launch_bounds__(512, 2)
void conv2_head_kernel(const float* __restrict__ trkF, const float* __restrict__ f1,
                       const float* __restrict__ U,    const float* __restrict__ Wbot2,
                       const float* __restrict__ bc2,
                       const float* __restrict__ Wo1, const float* __restrict__ bo1,
                       const float* __restrict__ Wo2, const float* __restrict__ bo2,
                       const float* __restrict__ Wo3, const float* __restrict__ bo3,
                       const float* __restrict__ Wo4, const float* __restrict__ bo4,
                       float* __restrict__ out, int out_size)
{
    extern __shared__ float sm[];
    float* dsh = sm;                    // 64*130 (trk; later V2)
    float* ssh = dsh + 64 * 130;        // 64*130 (f1)
    float* sc  = ssh + 64 * 130;        // 64*65 (scores; later W chunk, needs 4096 <= 4160)
    float* sn2 = sc + 64 * 65;          // 64
    float* colsum = sn2 + 64;           // 512
    float* pooled = colsum + 512;       // 128
    float* h1 = pooled + 128;           // 64
    float* h2 = h1 + 64;                // 32
    float* h3 = h2 + 32;                // 4
    int*  idxs = (int*)(h3 + 4);        // 64*8

    const int g   = blockIdx.x;
    const int tid = threadIdx.x;
    const int wid = tid >> 5, lane = tid & 31;
    const int tx  = tid & 15, ty = tid >> 4;   // ty: 0..31
    const float* dg = trkF + (size_t)g * 64 * 128;
    const float* sg = f1   + (size_t)g * 64 * 128;
    const float* Ug = U    + (size_t)g * 64 * 128;

    for (int t = tid; t < 64 * 128; t += 512) {
        int r = t >> 7, c = t & 127;
        dsh[r * 130 + c] = dg[t];
        ssh[r * 130 + c] = sg[t];
    }
    __syncthreads();

    // f1 squared norms
    #pragma unroll
    for (int q = 0; q < 4; q++) {
        int row = wid * 4 + q;
        const float* rp = &ssh[row * 130];
        float e0 = rp[lane], e1 = rp[32 + lane], e2 = rp[64 + lane], e3 = rp[96 + lane];
        float s = e0*e0 + e1*e1 + e2*e2 + e3*e3;
        #pragma unroll
        for (int off = 16; off > 0; off >>= 1) s += __shfl_xor_sync(~0u, s, off);
        if (lane == 0) sn2[row] = s;
    }
    __syncthreads();

    // scores = ||f_j||^2 - 2 dot(trk_i, f_j)
    {
        u64 acc[2][4];
        #pragma unroll
        for (int a = 0; a < 2; a++)
            #pragma unroll
            for (int b = 0; b < 4; b++) acc[a][b] = 0ull;
        #pragma unroll 8
        for (int kk = 0; kk < 64; kk++) {
            u64 av0 = *(const u64*)&dsh[(ty * 2) * 130 + kk * 2];
            u64 av1 = *(const u64*)&dsh[(ty * 2 + 1) * 130 + kk * 2];
            #pragma unroll
            for (int jj = 0; jj < 4; jj++) {
                u64 bv = *(const u64*)&ssh[(tx + jj * 16) * 130 + kk * 2];
                ffma2(acc[0][jj], av0, bv);
                ffma2(acc[1][jj], av1, bv);
            }
        }
        #pragma unroll
        for (int ii = 0; ii < 2; ii++)
            #pragma unroll
            for (int jj = 0; jj < 4; jj++) {
                float2 p = unpack2(acc[ii][jj]);
                int j = tx + jj * 16;
                sc[(ty * 2 + ii) * 65 + j] = sn2[j] - 2.f * (p.x + p.y);
            }
    }
    __syncthreads();

    // warp-parallel top-8 over 64 candidates (2 per lane)
    #pragma unroll
    for (int q = 0; q < 4; q++) {
        int row = wid * 4 + q;
        float v0 = sc[row * 65 + lane];
        float v1 = sc[row * 65 + 32 + lane];
        #pragma unroll
        for (int n = 0; n < KNN; n++) {
            float cv; int ci;
            if (v1 < v0) { cv = v1; ci = lane + 32; }
            else         { cv = v0; ci = lane; }
            #pragma unroll
            for (int off = 16; off > 0; off >>= 1) {
                float ov = __shfl_xor_sync(~0u, cv, off);
                int   oi = __shfl_xor_sync(~0u, ci, off);
                if (ov < cv || (ov == cv && oi < ci)) { cv = ov; ci = oi; }
            }
            if (lane == 0) idxs[row * 8 + n] = ci;
            if (ci == lane)           v0 = FLT_MAX;
            else if (ci == lane + 32) v1 = FLT_MAX;
        }
    }
    __syncthreads();   // topk done: sc free for W chunks; trk (dsh) dead

    // ---- V2 = f1 @ Wbot2, in-block: rows {2ty, 2ty+1}, cols 2tx+32j ----
    {
        u64 accv[2][4];
        #pragma unroll
        for (int a = 0; a < 2; a++)
            #pragma unroll
            for (int b = 0; b < 4; b++) accv[a][b] = 0ull;
        const int r0 = 2 * ty, r1 = 2 * ty + 1;
        for (int kc = 0; kc < 4; kc++) {
            // stage 32x128 weight chunk into sc
            #pragma unroll
            for (int e = 0; e < 2; e++) {
                int i4 = tid + e * 512;
                ((float4*)sc)[i4] = ((const float4*)Wbot2)[kc * 1024 + i4];
            }
            __syncthreads();
            #pragma unroll 4
            for (int kk = 0; kk < 32; kk++) {
                int k = kc * 32 + kk;
                u64 s0 = splat2(ssh[r0 * 130 + k]);
                u64 s1 = splat2(ssh[r1 * 130 + k]);
                const u64* br = (const u64*)&sc[kk * 128];
                u64 b0 = br[tx], b1 = br[tx + 16], b2 = br[tx + 32], b3 = br[tx + 48];
                ffma2(accv[0][0],s0,b0); ffma2(accv[0][1],s0,b1); ffma2(accv[0][2],s0,b2); ffma2(accv[0][3],s0,b3);
                ffma2(accv[1][0],s1,b0); ffma2(accv[1][1],s1,b1); ffma2(accv[1][2],s1,b2); ffma2(accv[1][3],s1,b3);
            }
            __syncthreads();
        }
        // write V2 over trk tile (ld 130)
        #pragma unroll
        for (int ii = 0; ii < 2; ii++) {
            int r = 2 * ty + ii;
            #pragma unroll
            for (int j = 0; j < 4; j++) {
                float2 p = unpack2(accv[ii][j]);
                *(float2*)&dsh[r * 130 + 2 * tx + 32 * j] = p;
            }
        }
    }
    __syncthreads();

    // combine: elu(U(+bc2) + max_n V2[idx]) + column sums
    {
        int c = tid & 127, ih = tid >> 7;
        float bc = bc2[c];
        float csum = 0.f;
        for (int i0 = 0; i0 < 64; i0 += 4) {
            int i = i0 + ih;
            const int* ip = &idxs[i * 8];
            float vmax = -FLT_MAX;
            #pragma unroll
            for (int n = 0; n < KNN; n++) vmax = fmaxf(vmax, dsh[ip[n] * 130 + c]);
            csum += eluf(Ug[i * 128 + c] + bc + vmax);
        }
        colsum[ih * 128 + c] = csum;
    }
    __syncthreads();
    if (tid < 128)
        pooled[tid] = (colsum[tid] + colsum[128 + tid] + colsum[256 + tid] + colsum[384 + tid]) * (1.f / 64.f);
    __syncthreads();
    if (tid < 64) {
        float a = bo1[tid];
        #pragma unroll 8
        for (int d = 0; d < 128; d++) a += pooled[d] * Wo1[d * 64 + tid];
        h1[tid] = eluf(a);
    }
    __syncthreads();
    if (tid < 32) {
        float a = bo2[tid];
        #pragma unroll 8
        for (int d = 0; d < 64; d++) a += h1[d] * Wo2[d * 32 + tid];
        h2[tid] = eluf(a);
    }
    __syncthreads();
    if (tid < 4) {
        float a = bo3[tid];
        #pragma unroll
        for (int d = 0; d < 32; d++) a += h2[d] * Wo3[d * 4 + tid];
        h3[tid] = eluf(a);
    }
    __syncthreads();
    if (tid == 0) {
        float a = bo4[0];
        #pragma unroll
        for (int d = 0; d < 4; d++) a += h3[d] * Wo4[d];
        out[g] = a;
        if (out_size >= 2 * G) out[G + g] = (float)g;
    }
}

// ---------------- launch ----------------
extern "C" void kernel_launch(void* const* d_in, const int* in_sizes, int n_in,
                              void* d_out, int out_size)
{
    const float* x_sv   = (const float*)d_in[0];
    const float* x_trk  = (const float*)d_in[1];
    const float* W_sv1  = (const float*)d_in[2];
    const float* b_sv1  = (const float*)d_in[3];
    const float* W_sv2  = (const float*)d_in[4];
    const float* b_sv2  = (const float*)d_in[5];
    const float* W_trk1 = (const float*)d_in[6];
    const float* b_trk1 = (const float*)d_in[7];
    const float* W_trk2 = (const float*)d_in[8];
    const float* b_trk2 = (const float*)d_in[9];
    const float* W_c1   = (const float*)d_in[10];
    const float* b_c1   = (const float*)d_in[11];
    const float* W_c2   = (const float*)d_in[12];
    const float* b_c2   = (const float*)d_in[13];
    const float* W_o1   = (const float*)d_in[14];
    const float* b_o1   = (const float*)d_in[15];
    const float* W_o2   = (const float*)d_in[16];
    const float* b_o2   = (const float*)d_in[17];
    const float* W_o3   = (const float*)d_in[18];
    const float* b_o3   = (const float*)d_in[19];
    const float* W_o4   = (const float*)d_in[20];
    const float* b_o4   = (const float*)d_in[21];
    float* out = (float*)d_out;

    float *p_sv, *p_trk, *p_U1, *p_U2, *p_V1, *p_f1, *p_Wd1, *p_Wd2;
    cudaGetSymbolAddress((void**)&p_sv,  g_sv);
    cudaGetSymbolAddress((void**)&p_trk, g_trk);
    cudaGetSymbolAddress((void**)&p_U1,  g_U1);
    cudaGetSymbolAddress((void**)&p_U2,  g_U2);
    cudaGetSymbolAddress((void**)&p_V1,  g_V1);
    cudaGetSymbolAddress((void**)&p_f1,  g_f1);
    cudaGetSymbolAddress((void**)&p_Wd1, g_Wd1);
    cudaGetSymbolAddress((void**)&p_Wd2, g_Wd2);

    const int smem_a = (16896 + 8192 + 128*2 + 2*128 + 128) * 4;
    const int smem_b = (16896 + 8192 + 128*8 + 8*128 + 128) * 4;
    const int smem_c = (64*130 + 16*130 + 16*130 + 64*17 + 16) * 4 + 64*8*4;
    const int smem_d = (64*130 + 64*130 + 64*65 + 64 + 512 + 128 + 64 + 32 + 4) * 4 + 64*8*4;

    (void)cudaFuncSetAttribute(node_kernel<2,2>,  cudaFuncAttributeMaxDynamicSharedMemorySize, smem_a);
    (void)cudaFuncSetAttribute(node_kernel<8,3>,  cudaFuncAttributeMaxDynamicSharedMemorySize, smem_b);
    (void)cudaFuncSetAttribute(conv1_kernel,      cudaFuncAttributeMaxDynamicSharedMemorySize, smem_c);
    (void)cudaFuncSetAttribute(conv2_head_kernel, cudaFuncAttributeMaxDynamicSharedMemorySize, smem_d);

    // 0: precompute diff weights (Wtop - Wbot) for both convs
    diff_kernel<<<64, 256>>>(W_c1, W_c2, p_Wd1, p_Wd2);

    // A: sv MLP + V1 (pass2 weight = Wc1 bottom half)
    node_kernel<2,2><<<G * NSV / 128, 256, smem_a>>>(
        x_sv, W_sv1, b_sv1, W_sv2, b_sv2, W_c1 + 16384, nullptr, nullptr, nullptr,
        p_sv, p_V1, nullptr);

    // B: trk MLP + U1 + U2 (pass2/3 weights = precomputed diffs)
    node_kernel<8,3><<<G * NTRK / 128, 256, smem_b>>>(
        x_trk, W_trk1, b_trk1, W_trk2, b_trk2, p_Wd1, b_c1, p_Wd2, b_c2,
        p_trk, p_U1, p_U2);

    // C: conv1 -> f1
    conv1_kernel<<<G, 256, smem_c>>>(p_trk, p_sv, p_U1, p_V1, p_f1);

    // D: conv2 (+ fused V2 GEMM) + head
    conv2_head_kernel<<<G, 512, smem_d>>>(p_trk, p_f1, p_U2,
        W_c2 + 16384, b_c2,
        W_o1, b_o1, W_o2, b_o2, W_o3, b_o3, W_o4, b_o4, out, out_size);
}

// round 13
// speedup vs baseline: 1.0854x; 1.0315x over previous
#include <cuda_runtime.h>
#include <math.h>
#include <float.h>

#define G    1024
#define NSV  16
#define NTRK 64
#define KNN  8

typedef unsigned long long u64;

// ---------------- scratch (static device globals: no allocation) ----------------
__device__ float g_trk[G*NTRK*128];
__device__ float g_U2 [G*NTRK*128];
__device__ float g_f1 [G*NTRK*128];
__device__ float g_Wd1[128*128];   // Wc1_top - Wc1_bot
__device__ float g_Wd2[128*128];   // Wc2_top - Wc2_bot

__device__ __forceinline__ float eluf(float x) { return x > 0.f ? x : expm1f(x); }

// ---- packed f32x2 helpers ----
__device__ __forceinline__ u64 splat2(float a) {
    u64 r; asm("mov.b64 %0, {%1, %1};" : "=l"(r) : "f"(a)); return r;
}
__device__ __forceinline__ void ffma2(u64& c, u64 a, u64 b) {
    asm("fma.rn.f32x2 %0, %1, %2, %0;" : "+l"(c) : "l"(a), "l"(b));
}
__device__ __forceinline__ float2 unpack2(u64 v) {
    float2 f; asm("mov.b64 {%0, %1}, %2;" : "=f"(f.x), "=f"(f.y) : "l"(v)); return f;
}

// ---- plain 32x128 weight chunk staging (LDG->STS), 256 threads ----
__device__ __forceinline__ void stage_chunk(float* dst, const float* __restrict__ W,
                                            int kc, int tid)
{
    #pragma unroll
    for (int e = 0; e < 4; e++) {
        int i4 = tid + e * 256;               // 0..1023 float4s = 32x128 chunk
        ((float4*)dst)[i4] = ((const float4*)W)[kc * 1024 + i4];
    }
}

// ---- GEMM core over one 32-k chunk, 256 threads, 8x8 microtile (node kernel) ----
__device__ __forceinline__ void zero_acc8(u64 acc[8][4]) {
    #pragma unroll
    for (int i = 0; i < 8; i++)
        #pragma unroll
        for (int j = 0; j < 4; j++) acc[i][j] = 0ull;
}
__device__ __forceinline__ void gemm_chunk(const float* __restrict__ Hs,
                                           const float* __restrict__ Ws,
                                           u64 acc[8][4], int tx, int ty)
{
    #pragma unroll 4
    for (int kk = 0; kk < 32; kk++) {
        const float* arow = &Hs[kk * 132 + ty * 8];
        float4 a0 = *(const float4*)arow;
        float4 a1 = *(const float4*)(arow + 4);
        const u64* br = (const u64*)&Ws[kk * 128];
        u64 b0 = br[tx], b1 = br[tx + 16], b2 = br[tx + 32], b3 = br[tx + 48];
        u64 s;
        s = splat2(a0.x); ffma2(acc[0][0],s,b0); ffma2(acc[0][1],s,b1); ffma2(acc[0][2],s,b2); ffma2(acc[0][3],s,b3);
        s = splat2(a0.y); ffma2(acc[1][0],s,b0); ffma2(acc[1][1],s,b1); ffma2(acc[1][2],s,b2); ffma2(acc[1][3],s,b3);
        s = splat2(a0.z); ffma2(acc[2][0],s,b0); ffma2(acc[2][1],s,b1); ffma2(acc[2][2],s,b2); ffma2(acc[2][3],s,b3);
        s = splat2(a0.w); ffma2(acc[3][0],s,b0); ffma2(acc[3][1],s,b1); ffma2(acc[3][2],s,b2); ffma2(acc[3][3],s,b3);
        s = splat2(a1.x); ffma2(acc[4][0],s,b0); ffma2(acc[4][1],s,b1); ffma2(acc[4][2],s,b2); ffma2(acc[4][3],s,b3);
        s = splat2(a1.y); ffma2(acc[5][0],s,b0); ffma2(acc[5][1],s,b1); ffma2(acc[5][2],s,b2); ffma2(acc[5][3],s,b3);
        s = splat2(a1.z); ffma2(acc[6][0],s,b0); ffma2(acc[6][1],s,b1); ffma2(acc[6][2],s,b2); ffma2(acc[6][3],s,b3);
        s = splat2(a1.w); ffma2(acc[7][0],s,b0); ffma2(acc[7][1],s,b1); ffma2(acc[7][2],s,b2); ffma2(acc[7][3],s,b3);
    }
}
__device__ __forceinline__ void gemm_pass(const float* __restrict__ Hs, float* Wb,
                                          const float* __restrict__ W,
                                          u64 acc[8][4], int tid, int tx, int ty)
{
    stage_chunk(Wb, W, 0, tid);
    __syncthreads();
    #pragma unroll
    for (int kc = 0; kc < 4; kc++) {
        if (kc < 3) stage_chunk(Wb + ((kc + 1) & 1) * 4096, W, kc + 1, tid);
        gemm_chunk(Hs + kc * 32 * 132, Wb + (kc & 1) * 4096, acc, tx, ty);
        __syncthreads();
    }
}
__device__ __forceinline__ void store256(const u64 acc[8][4], float* __restrict__ C,
                                         size_t row0, int tx, int ty,
                                         const float* __restrict__ bias)
{
    float2 bv[4] = {{0,0},{0,0},{0,0},{0,0}};
    if (bias) {
        #pragma unroll
        for (int j = 0; j < 4; j++) bv[j] = *(const float2*)&bias[tx * 2 + j * 32];
    }
    #pragma unroll
    for (int ii = 0; ii < 8; ii++) {
        size_t r = row0 + ty * 8 + ii;
        #pragma unroll
        for (int j = 0; j < 4; j++) {
            float2 p = unpack2(acc[ii][j]);
            p.x += bv[j].x; p.y += bv[j].y;
            *(float2*)&C[r * 128 + tx * 2 + j * 32] = p;
        }
    }
}

// ---------------- diff-weight precompute ----------------
__global__ __launch_bounds__(256)
void diff_kernel(const float* __restrict__ Wc1, const float* __restrict__ Wc2,
                 float* __restrict__ D1, float* __restrict__ D2)
{
    int i = blockIdx.x * 256 + threadIdx.x;
    D1[i] = Wc1[i] - Wc1[i + 16384];
    D2[i] = Wc2[i] - Wc2[i + 16384];
}

// =====================================================================
// trk node kernel: layer1 -> Hs; feats = relu(Hs@W2+b2) -> Yf + Hs;
// U2 = feats @ Wd2 (NO bias; bc2 added in conv2). 256 thr, 2 blocks/SM.
// =====================================================================
__global__ __launch_bounds__(256, 2)
void trk_kernel(const float* __restrict__ X,
                const float* __restrict__ W1, const float* __restrict__ b1,
                const float* __restrict__ W2, const float* __restrict__ b2,
                const float* __restrict__ Wd2,
                float* __restrict__ Yf, float* __restrict__ Yu2)
{
    extern __shared__ float sm[];
    float* Hs  = sm;                    // 128*132 = 16896
    float* Wb  = Hs + 16896;            // 2*4096
    float* Xin = Wb + 8192;             // 128*8
    float* W1s = Xin + 1024;            // 8*128
    float* b1s = W1s + 1024;            // 128
    const int tid = threadIdx.x;
    const int tx = tid & 15, ty = tid >> 4;
    const size_t row0 = (size_t)blockIdx.x * 128;

    for (int t = tid; t < 1024; t += 256) Xin[t] = X[row0 * 8 + t];
    for (int t = tid; t < 1024; t += 256) W1s[t] = W1[t];
    if (tid < 128) b1s[tid] = b1[tid];
    __syncthreads();

    // layer 1 -> Hs transposed [c][r]
    {
        int r = tid >> 1, ch = (tid & 1) * 64;
        float xr[8];
        #pragma unroll
        for (int d = 0; d < 8; d++) xr[d] = Xin[r * 8 + d];
        #pragma unroll 4
        for (int cc = 0; cc < 64; cc++) {
            int c = ch + cc;
            float a = b1s[c];
            #pragma unroll
            for (int d = 0; d < 8; d++) a = fmaf(xr[d], W1s[d * 128 + c], a);
            Hs[c * 132 + r] = eluf(a);
        }
    }

    u64 acc[8][4];
    zero_acc8(acc);
    gemm_pass(Hs, Wb, W2, acc, tid, tx, ty);

    // feats = relu(acc + b2) -> Yf and Hs (transposed, in place)
    {
        float2 bv[4];
        #pragma unroll
        for (int j = 0; j < 4; j++) bv[j] = *(const float2*)&b2[tx * 2 + j * 32];
        #pragma unroll
        for (int ii = 0; ii < 8; ii++) {
            int rr = ty * 8 + ii;
            #pragma unroll
            for (int j = 0; j < 4; j++) {
                float2 p = unpack2(acc[ii][j]);
                float va = fmaxf(p.x + bv[j].x, 0.f);
                float vb = fmaxf(p.y + bv[j].y, 0.f);
                int c = tx * 2 + j * 32;
                float2 o = {va, vb};
                *(float2*)&Yf[(row0 + rr) * 128 + c] = o;
                Hs[c * 132 + rr]       = va;
                Hs[(c + 1) * 132 + rr] = vb;
            }
        }
    }
    __syncthreads();

    zero_acc8(acc);
    gemm_pass(Hs, Wb, Wd2, acc, tid, tx, ty);
    store256(acc, Yu2, row0, tx, ty, nullptr);
}

// =====================================================================
// conv1 (FULLY FUSED): sv MLP + V1 + U1 computed in-block.
// 256 threads/graph, ~74KB smem -> 3 blocks/SM.
// f1 = elu(trk@Wd1 + bc1 + max_knn(svfeat@Wbot1))
// =====================================================================
__global__ __launch_bounds__(256, 3)
void conv1_fused(const float* __restrict__ trkF, const float* __restrict__ x_sv,
                 const float* __restrict__ Wsv1, const float* __restrict__ bsv1,
                 const float* __restrict__ Wsv2, const float* __restrict__ bsv2,
                 const float* __restrict__ Wd1,  const float* __restrict__ bc1g,
                 const float* __restrict__ Wbot1,
                 float* __restrict__ f1out)
{
    extern __shared__ float sm[];
    float* dsh  = sm;                  // 64*130 trk
    float* ssh  = dsh + 8320;          // 16*130 sv feats
    float* vsh  = ssh + 2080;          // 16*130 hidden, then V1
    float* Wbuf = vsh + 2080;          // 4096 weight chunk
    float* sc   = Wbuf + 4096;         // 64*17 scores
    float* sn2  = sc + 1088;           // 16
    float* S    = sn2 + 16;            // 672 smalls
    int*  idxs  = (int*)(S + 672);     // 512 ints

    float* xsv = S;          // 32
    float* w1  = S + 32;     // 256
    float* b1  = S + 288;    // 128
    float* b2  = S + 416;    // 128
    float* bc1 = S + 544;    // 128

    const int tid = threadIdx.x;
    const int tx = tid & 15, ty = tid >> 4;       // ty: 0..15
    const int lane = tid & 31, wid = tid >> 5;
    const int g = blockIdx.x;
    const float* dg = trkF + (size_t)g * 64 * 128;

    for (int t = tid; t < 64 * 128; t += 256)
        dsh[(t >> 7) * 130 + (t & 127)] = dg[t];
    if (tid < 32) xsv[tid] = x_sv[g * 32 + tid];
    w1[tid] = Wsv1[tid];
    if (tid < 128) { b1[tid] = bsv1[tid]; b2[tid] = bsv2[tid]; bc1[tid] = bc1g[tid]; }
    __syncthreads();

    // sv layer1 -> vsh (16 x 128 row-major, ld 130)
    {
        float x0 = xsv[ty * 2], x1 = xsv[ty * 2 + 1];
        #pragma unroll
        for (int j = 0; j < 4; j++) {
            int c = 2 * tx + 32 * j;
            vsh[ty * 130 + c]     = eluf(b1[c]     + x0 * w1[c]       + x1 * w1[128 + c]);
            vsh[ty * 130 + c + 1] = eluf(b1[c + 1] + x0 * w1[c + 1]   + x1 * w1[128 + c + 1]);
        }
    }
    __syncthreads();

    // sv layer2 (streamed Wsv2) -> ssh = relu(...)
    {
        u64 a[4] = {0ull, 0ull, 0ull, 0ull};
        for (int kc = 0; kc < 4; kc++) {
            stage_chunk(Wbuf, Wsv2, kc, tid);
            __syncthreads();
            #pragma unroll 4
            for (int kk = 0; kk < 32; kk++) {
                u64 s = splat2(vsh[ty * 130 + kc * 32 + kk]);
                const u64* br = (const u64*)&Wbuf[kk * 128];
                ffma2(a[0], s, br[tx]);      ffma2(a[1], s, br[tx + 16]);
                ffma2(a[2], s, br[tx + 32]); ffma2(a[3], s, br[tx + 48]);
            }
            __syncthreads();
        }
        #pragma unroll
        for (int j = 0; j < 4; j++) {
            float2 p = unpack2(a[j]);
            int c = 2 * tx + 32 * j;
            ssh[ty * 130 + c]     = fmaxf(p.x + b2[c],     0.f);
            ssh[ty * 130 + c + 1] = fmaxf(p.y + b2[c + 1], 0.f);
        }
    }
    __syncthreads();

    // sv squared norms: 8 warps x 2 rows
    #pragma unroll
    for (int q = 0; q < 2; q++) {
        int row = wid * 2 + q;
        const float* rp = &ssh[row * 130];
        float e0 = rp[lane], e1 = rp[32 + lane], e2 = rp[64 + lane], e3 = rp[96 + lane];
        float s = e0*e0 + e1*e1 + e2*e2 + e3*e3;
        #pragma unroll
        for (int off = 16; off > 0; off >>= 1) s += __shfl_xor_sync(~0u, s, off);
        if (lane == 0) sn2[row] = s;
    }
    __syncthreads();

    // scores: i = tid>>2 (64 rows), jj = tid&3 -> j = jj + 4m
    {
        int i = tid >> 2, jj = tid & 3;
        u64 a[4] = {0ull, 0ull, 0ull, 0ull};
        #pragma unroll 8
        for (int kk = 0; kk < 64; kk++) {
            u64 av = *(const u64*)&dsh[i * 130 + kk * 2];
            #pragma unroll
            for (int m = 0; m < 4; m++) {
                u64 bv = *(const u64*)&ssh[(jj + 4 * m) * 130 + kk * 2];
                ffma2(a[m], av, bv);
            }
        }
        #pragma unroll
        for (int m = 0; m < 4; m++) {
            float2 p = unpack2(a[m]);
            int j = jj + 4 * m;
            sc[i * 17 + j] = sn2[j] - 2.f * (p.x + p.y);
        }
    }
    __syncthreads();

    // warp-parallel top-8 (tie -> lowest index): warp w rows 8w..8w+7
    #pragma unroll
    for (int q = 0; q < 8; q++) {
        int row = wid * 8 + q;
        float mv = (lane < 16) ? sc[row * 17 + lane] : FLT_MAX;
        #pragma unroll
        for (int n = 0; n < KNN; n++) {
            float cv = mv; int ci = lane;
            #pragma unroll
            for (int off = 16; off > 0; off >>= 1) {
                float ov = __shfl_xor_sync(~0u, cv, off);
                int   oi = __shfl_xor_sync(~0u, ci, off);
                if (ov < cv || (ov == cv && oi < ci)) { cv = ov; ci = oi; }
            }
            if (lane == 0) idxs[row * 8 + n] = ci;
            if (lane == ci) mv = FLT_MAX;
        }
    }
    __syncthreads();

    // U1 = trk @ Wd1 -> registers (rows ty*4+ii, cols 2tx+32j)
    u64 accU[4][4];
    #pragma unroll
    for (int i = 0; i < 4; i++) { accU[i][0]=0; accU[i][1]=0; accU[i][2]=0; accU[i][3]=0; }
    for (int kc = 0; kc < 4; kc++) {
        stage_chunk(Wbuf, Wd1, kc, tid);
        __syncthreads();
        #pragma unroll 2
        for (int kk = 0; kk < 32; kk++) {
            const u64* br = (const u64*)&Wbuf[kk * 128];
            u64 b0 = br[tx], b1v = br[tx + 16], b2v = br[tx + 32], b3v = br[tx + 48];
            #pragma unroll
            for (int ii = 0; ii < 4; ii++) {
                u64 s = splat2(dsh[(ty * 4 + ii) * 130 + kc * 32 + kk]);
                ffma2(accU[ii][0], s, b0);  ffma2(accU[ii][1], s, b1v);
                ffma2(accU[ii][2], s, b2v); ffma2(accU[ii][3], s, b3v);
            }
        }
        __syncthreads();
    }

    // V1 = svfeat @ Wbot1 -> vsh (overwrites dead hidden)
    {
        u64 a[4] = {0ull, 0ull, 0ull, 0ull};
        for (int kc = 0; kc < 4; kc++) {
            stage_chunk(Wbuf, Wbot1, kc, tid);
            __syncthreads();
            #pragma unroll 4
            for (int kk = 0; kk < 32; kk++) {
                u64 s = splat2(ssh[ty * 130 + kc * 32 + kk]);
                const u64* br = (const u64*)&Wbuf[kk * 128];
                ffma2(a[0], s, br[tx]);      ffma2(a[1], s, br[tx + 16]);
                ffma2(a[2], s, br[tx + 32]); ffma2(a[3], s, br[tx + 48]);
            }
            __syncthreads();
        }
        #pragma unroll
        for (int j = 0; j < 4; j++) {
            float2 p = unpack2(a[j]);
            *(float2*)&vsh[ty * 130 + 2 * tx + 32 * j] = p;
        }
    }
    __syncthreads();

    // combine: f1 = elu(U1 + bc1 + max_n V1[idx])
    #pragma unroll
    for (int ii = 0; ii < 4; ii++) {
        int row = ty * 4 + ii;
        const int* ip = &idxs[row * 8];
        #pragma unroll
        for (int j = 0; j < 4; j++) {
            int c = 2 * tx + 32 * j;
            float mx = -FLT_MAX, my = -FLT_MAX;
            #pragma unroll
            for (int n = 0; n < KNN; n++) {
                float2 v = *(const float2*)&vsh[ip[n] * 130 + c];
                mx = fmaxf(mx, v.x); my = fmaxf(my, v.y);
            }
            float2 p = unpack2(accU[ii][j]);
            float2 o = { eluf(p.x + bc1[c] + mx), eluf(p.y + bc1[c + 1] + my) };
            *(float2*)&f1out[((size_t)g * 64 + row) * 128 + c] = o;
        }
    }
}

// =====================================================================
// conv2 (FUSED V2): scores + topk + V2 = f1 @ Wbot2 in-block + combine
// (adds bc2) + mean pool + head. 512 threads, 2 blocks/SM.
// =====================================================================
__global__ __launch_bounds__(512, 2)
void conv2_head_kernel(const float* __restrict__ trkF, const float* __restrict__ f1,
                       const float* __restrict__ U,    const float* __restrict__ Wbot2,
                       const float* __restrict__ bc2,
                       const float* __restrict__ Wo1, const float* __restrict__ bo1,
                       const float* __restrict__ Wo2, const float* __restrict__ bo2,
                       const float* __restrict__ Wo3, const float* __restrict__ bo3,
                       const float* __restrict__ Wo4, const float* __restrict__ bo4,
                       float* __restrict__ out, int out_size)
{
    extern __shared__ float sm[];
    float* dsh = sm;                    // 64*130 (trk; later V2)
    float* ssh = dsh + 64 * 130;        // 64*130 (f1)
    float* sc  = ssh + 64 * 130;        // 64*65 (scores; later W chunk)
    float* sn2 = sc + 64 * 65;          // 64
    float* colsum = sn2 + 64;           // 512
    float* pooled = colsum + 512;       // 128
    float* h1 = pooled + 128;           // 64
    float* h2 = h1 + 64;                // 32
    float* h3 = h2 + 32;                // 4
    int*  idxs = (int*)(h3 + 4);        // 64*8

    const int g   = blockIdx.x;
    const int tid = threadIdx.x;
    const int wid = tid >> 5, lane = tid & 31;
    const int tx  = tid & 15, ty = tid >> 4;   // ty: 0..31
    const float* dg = trkF + (size_t)g * 64 * 128;
    const float* sg = f1   + (size_t)g * 64 * 128;
    const float* Ug = U    + (size_t)g * 64 * 128;

    for (int t = tid; t < 64 * 128; t += 512) {
        int r = t >> 7, c = t & 127;
        dsh[r * 130 + c] = dg[t];
        ssh[r * 130 + c] = sg[t];
    }
    __syncthreads();

    #pragma unroll
    for (int q = 0; q < 4; q++) {
        int row = wid * 4 + q;
        const float* rp = &ssh[row * 130];
        float e0 = rp[lane], e1 = rp[32 + lane], e2 = rp[64 + lane], e3 = rp[96 + lane];
        float s = e0*e0 + e1*e1 + e2*e2 + e3*e3;
        #pragma unroll
        for (int off = 16; off > 0; off >>= 1) s += __shfl_xor_sync(~0u, s, off);
        if (lane == 0) sn2[row] = s;
    }
    __syncthreads();

    {
        u64 acc[2][4];
        #pragma unroll
        for (int a = 0; a < 2; a++)
            #pragma unroll
            for (int b = 0; b < 4; b++) acc[a][b] = 0ull;
        #pragma unroll 8
        for (int kk = 0; kk < 64; kk++) {
            u64 av0 = *(const u64*)&dsh[(ty * 2) * 130 + kk * 2];
            u64 av1 = *(const u64*)&dsh[(ty * 2 + 1) * 130 + kk * 2];
            #pragma unroll
            for (int jj = 0; jj < 4; jj++) {
                u64 bv = *(const u64*)&ssh[(tx + jj * 16) * 130 + kk * 2];
                ffma2(acc[0][jj], av0, bv);
                ffma2(acc[1][jj], av1, bv);
            }
        }
        #pragma unroll
        for (int ii = 0; ii < 2; ii++)
            #pragma unroll
            for (int jj = 0; jj < 4; jj++) {
                float2 p = unpack2(acc[ii][jj]);
                int j = tx + jj * 16;
                sc[(ty * 2 + ii) * 65 + j] = sn2[j] - 2.f * (p.x + p.y);
            }
    }
    __syncthreads();

    #pragma unroll
    for (int q = 0; q < 4; q++) {
        int row = wid * 4 + q;
        float v0 = sc[row * 65 + lane];
        float v1 = sc[row * 65 + 32 + lane];
        #pragma unroll
        for (int n = 0; n < KNN; n++) {
            float cv; int ci;
            if (v1 < v0) { cv = v1; ci = lane + 32; }
            else         { cv = v0; ci = lane; }
            #pragma unroll
            for (int off = 16; off > 0; off >>= 1) {
                float ov = __shfl_xor_sync(~0u, cv, off);
                int   oi = __shfl_xor_sync(~0u, ci, off);
                if (ov < cv || (ov == cv && oi < ci)) { cv = ov; ci = oi; }
            }
            if (lane == 0) idxs[row * 8 + n] = ci;
            if (ci == lane)           v0 = FLT_MAX;
            else if (ci == lane + 32) v1 = FLT_MAX;
        }
    }
    __syncthreads();   // topk done: sc free for W chunks; trk (dsh) dead

    // ---- V2 = f1 @ Wbot2, in-block ----
    {
        u64 accv[2][4];
        #pragma unroll
        for (int a = 0; a < 2; a++)
            #pragma unroll
            for (int b = 0; b < 4; b++) accv[a][b] = 0ull;
        const int r0 = 2 * ty, r1 = 2 * ty + 1;
        for (int kc = 0; kc < 4; kc++) {
            #pragma unroll
            for (int e = 0; e < 2; e++) {
                int i4 = tid + e * 512;
                ((float4*)sc)[i4] = ((const float4*)Wbot2)[kc * 1024 + i4];
            }
            __syncthreads();
            #pragma unroll 4
            for (int kk = 0; kk < 32; kk++) {
                int k = kc * 32 + kk;
                u64 s0 = splat2(ssh[r0 * 130 + k]);
                u64 s1 = splat2(ssh[r1 * 130 + k]);
                const u64* br = (const u64*)&sc[kk * 128];
                u64 b0 = br[tx], b1 = br[tx + 16], b2 = br[tx + 32], b3 = br[tx + 48];
                ffma2(accv[0][0],s0,b0); ffma2(accv[0][1],s0,b1); ffma2(accv[0][2],s0,b2); ffma2(accv[0][3],s0,b3);
                ffma2(accv[1][0],s1,b0); ffma2(accv[1][1],s1,b1); ffma2(accv[1][2],s1,b2); ffma2(accv[1][3],s1,b3);
            }
            __syncthreads();
        }
        #pragma unroll
        for (int ii = 0; ii < 2; ii++) {
            int r = 2 * ty + ii;
            #pragma unroll
            for (int j = 0; j < 4; j++) {
                float2 p = unpack2(accv[ii][j]);
                *(float2*)&dsh[r * 130 + 2 * tx + 32 * j] = p;
            }
        }
    }
    __syncthreads();

    // combine: elu(U + bc2 + max_n V2[idx]) + column sums
    {
        int c = tid & 127, ih = tid >> 7;
        float bc = bc2[c];
        float csum = 0.f;
        for (int i0 = 0; i0 < 64; i0 += 4) {
            int i = i0 + ih;
            const int* ip = &idxs[i * 8];
            float vmax = -FLT_MAX;
            #pragma unroll
            for (int n = 0; n < KNN; n++) vmax = fmaxf(vmax, dsh[ip[n] * 130 + c]);
            csum += eluf(Ug[i * 128 + c] + bc + vmax);
        }
        colsum[ih * 128 + c] = csum;
    }
    __syncthreads();
    if (tid < 128)
        pooled[tid] = (colsum[tid] + colsum[128 + tid] + colsum[256 + tid] + colsum[384 + tid]) * (1.f / 64.f);
    __syncthreads();
    if (tid < 64) {
        float a = bo1[tid];
        #pragma unroll 8
        for (int d = 0; d < 128; d++) a += pooled[d] * Wo1[d * 64 + tid];
        h1[tid] = eluf(a);
    }
    __syncthreads();
    if (tid < 32) {
        float a = bo2[tid];
        #pragma unroll 8
        for (int d = 0; d < 64; d++) a += h1[d] * Wo2[d * 32 + tid];
        h2[tid] = eluf(a);
    }
    __syncthreads();
    if (tid < 4) {
        float a = bo3[tid];
        #pragma unroll
        for (int d = 0; d < 32; d++) a += h2[d] * Wo3[d * 4 + tid];
        h3[tid] = eluf(a);
    }
    __syncthreads();
    if (tid == 0) {
        float a = bo4[0];
        #pragma unroll
        for (int d = 0; d < 4; d++) a += h3[d] * Wo4[d];
        out[g] = a;
        if (out_size >= 2 * G) out[G + g] = (float)g;
    }
}

// ---------------- launch ----------------
extern "C" void kernel_launch(void* const* d_in, const int* in_sizes, int n_in,
                              void* d_out, int out_size)
{
    const float* x_sv   = (const float*)d_in[0];
    const float* x_trk  = (const float*)d_in[1];
    const float* W_sv1  = (const float*)d_in[2];
    const float* b_sv1  = (const float*)d_in[3];
    const float* W_sv2  = (const float*)d_in[4];
    const float* b_sv2  = (const float*)d_in[5];
    const float* W_trk1 = (const float*)d_in[6];
    const float* b_trk1 = (const float*)d_in[7];
    const float* W_trk2 = (const float*)d_in[8];
    const float* b_trk2 = (const float*)d_in[9];
    const float* W_c1   = (const float*)d_in[10];
    const float* b_c1   = (const float*)d_in[11];
    const float* W_c2   = (const float*)d_in[12];
    const float* b_c2   = (const float*)d_in[13];
    const float* W_o1   = (const float*)d_in[14];
    const float* b_o1   = (const float*)d_in[15];
    const float* W_o2   = (const float*)d_in[16];
    const float* b_o2   = (const float*)d_in[17];
    const float* W_o3   = (const float*)d_in[18];
    const float* b_o3   = (const float*)d_in[19];
    const float* W_o4   = (const float*)d_in[20];
    const float* b_o4   = (const float*)d_in[21];
    float* out = (float*)d_out;

    float *p_trk, *p_U2, *p_f1, *p_Wd1, *p_Wd2;
    cudaGetSymbolAddress((void**)&p_trk, g_trk);
    cudaGetSymbolAddress((void**)&p_U2,  g_U2);
    cudaGetSymbolAddress((void**)&p_f1,  g_f1);
    cudaGetSymbolAddress((void**)&p_Wd1, g_Wd1);
    cudaGetSymbolAddress((void**)&p_Wd2, g_Wd2);

    const int smem_b  = (16896 + 8192 + 1024 + 1024 + 128) * 4;
    const int smem_c1 = (8320 + 2080 + 2080 + 4096 + 1088 + 16 + 672) * 4 + 512 * 4;
    const int smem_d  = (64*130 + 64*130 + 64*65 + 64 + 512 + 128 + 64 + 32 + 4) * 4 + 64*8*4;

    (void)cudaFuncSetAttribute(trk_kernel,        cudaFuncAttributeMaxDynamicSharedMemorySize, smem_b);
    (void)cudaFuncSetAttribute(conv1_fused,       cudaFuncAttributeMaxDynamicSharedMemorySize, smem_c1);
    (void)cudaFuncSetAttribute(conv2_head_kernel, cudaFuncAttributeMaxDynamicSharedMemorySize, smem_d);

    // 0: diff weights
    diff_kernel<<<64, 256>>>(W_c1, W_c2, p_Wd1, p_Wd2);

    // B: trk MLP + U2 (no bias; bc2 added in conv2)
    trk_kernel<<<G * NTRK / 128, 256, smem_b>>>(
        x_trk, W_trk1, b_trk1, W_trk2, b_trk2, p_Wd2, p_trk, p_U2);

    // C: conv1 fully fused (sv MLP + V1 + U1 in-block) -> f1
    conv1_fused<<<G, 256, smem_c1>>>(
        p_trk, x_sv, W_sv1, b_sv1, W_sv2, b_sv2,
        p_Wd1, b_c1, W_c1 + 16384, p_f1);

    // D: conv2 (+ fused V2) + head
    conv2_head_kernel<<<G, 512, smem_d>>>(p_trk, p_f1, p_U2,
        W_c2 + 16384, b_c2,
        W_o1, b_o1, W_o2, b_o2, W_o3, b_o3, W_o4, b_o4, out, out_size);
}

// round 14
// speedup vs baseline: 1.1008x; 1.0142x over previous
#include <cuda_runtime.h>
#include <math.h>
#include <float.h>

#define G    1024
#define NSV  16
#define NTRK 64
#define KNN  8

typedef unsigned long long u64;

// ---------------- scratch (static device globals: no allocation) ----------------
__device__ float g_trk[G*NTRK*128];
__device__ float g_U2 [G*NTRK*128];
__device__ float g_f1 [G*NTRK*128];
__device__ float g_Wd1[128*128];   // Wc1_top - Wc1_bot
__device__ float g_Wd2[128*128];   // Wc2_top - Wc2_bot

__device__ __forceinline__ float eluf(float x) { return x > 0.f ? x : expm1f(x); }

// ---- packed f32x2 helpers ----
__device__ __forceinline__ u64 splat2(float a) {
    u64 r; asm("mov.b64 %0, {%1, %1};" : "=l"(r) : "f"(a)); return r;
}
__device__ __forceinline__ u64 pack2f(float x, float y) {
    u64 r; asm("mov.b64 %0, {%1, %2};" : "=l"(r) : "f"(x), "f"(y)); return r;
}
__device__ __forceinline__ void ffma2(u64& c, u64 a, u64 b) {
    asm("fma.rn.f32x2 %0, %1, %2, %0;" : "+l"(c) : "l"(a), "l"(b));
}
__device__ __forceinline__ float2 unpack2(u64 v) {
    float2 f; asm("mov.b64 {%0, %1}, %2;" : "=f"(f.x), "=f"(f.y) : "l"(v)); return f;
}

// ---- plain 32x128 weight chunk staging (LDG->STS), 256 threads ----
__device__ __forceinline__ void stage_chunk(float* dst, const float* __restrict__ W,
                                            int kc, int tid)
{
    #pragma unroll
    for (int e = 0; e < 4; e++) {
        int i4 = tid + e * 256;
        ((float4*)dst)[i4] = ((const float4*)W)[kc * 1024 + i4];
    }
}

// ---- GEMM core over one 32-k chunk, 256 threads, 8x8 microtile (trk kernel) ----
__device__ __forceinline__ void zero_acc8(u64 acc[8][4]) {
    #pragma unroll
    for (int i = 0; i < 8; i++)
        #pragma unroll
        for (int j = 0; j < 4; j++) acc[i][j] = 0ull;
}
__device__ __forceinline__ void gemm_chunk(const float* __restrict__ Hs,
                                           const float* __restrict__ Ws,
                                           u64 acc[8][4], int tx, int ty)
{
    #pragma unroll 4
    for (int kk = 0; kk < 32; kk++) {
        const float* arow = &Hs[kk * 132 + ty * 8];
        float4 a0 = *(const float4*)arow;
        float4 a1 = *(const float4*)(arow + 4);
        const u64* br = (const u64*)&Ws[kk * 128];
        u64 b0 = br[tx], b1 = br[tx + 16], b2 = br[tx + 32], b3 = br[tx + 48];
        u64 s;
        s = splat2(a0.x); ffma2(acc[0][0],s,b0); ffma2(acc[0][1],s,b1); ffma2(acc[0][2],s,b2); ffma2(acc[0][3],s,b3);
        s = splat2(a0.y); ffma2(acc[1][0],s,b0); ffma2(acc[1][1],s,b1); ffma2(acc[1][2],s,b2); ffma2(acc[1][3],s,b3);
        s = splat2(a0.z); ffma2(acc[2][0],s,b0); ffma2(acc[2][1],s,b1); ffma2(acc[2][2],s,b2); ffma2(acc[2][3],s,b3);
        s = splat2(a0.w); ffma2(acc[3][0],s,b0); ffma2(acc[3][1],s,b1); ffma2(acc[3][2],s,b2); ffma2(acc[3][3],s,b3);
        s = splat2(a1.x); ffma2(acc[4][0],s,b0); ffma2(acc[4][1],s,b1); ffma2(acc[4][2],s,b2); ffma2(acc[4][3],s,b3);
        s = splat2(a1.y); ffma2(acc[5][0],s,b0); ffma2(acc[5][1],s,b1); ffma2(acc[5][2],s,b2); ffma2(acc[5][3],s,b3);
        s = splat2(a1.z); ffma2(acc[6][0],s,b0); ffma2(acc[6][1],s,b1); ffma2(acc[6][2],s,b2); ffma2(acc[6][3],s,b3);
        s = splat2(a1.w); ffma2(acc[7][0],s,b0); ffma2(acc[7][1],s,b1); ffma2(acc[7][2],s,b2); ffma2(acc[7][3],s,b3);
    }
}
__device__ __forceinline__ void gemm_pass(const float* __restrict__ Hs, float* Wb,
                                          const float* __restrict__ W,
                                          u64 acc[8][4], int tid, int tx, int ty)
{
    stage_chunk(Wb, W, 0, tid);
    __syncthreads();
    #pragma unroll
    for (int kc = 0; kc < 4; kc++) {
        if (kc < 3) stage_chunk(Wb + ((kc + 1) & 1) * 4096, W, kc + 1, tid);
        gemm_chunk(Hs + kc * 32 * 132, Wb + (kc & 1) * 4096, acc, tx, ty);
        __syncthreads();
    }
}
__device__ __forceinline__ void store256(const u64 acc[8][4], float* __restrict__ C,
                                         size_t row0, int tx, int ty,
                                         const float* __restrict__ bias)
{
    float2 bv[4] = {{0,0},{0,0},{0,0},{0,0}};
    if (bias) {
        #pragma unroll
        for (int j = 0; j < 4; j++) bv[j] = *(const float2*)&bias[tx * 2 + j * 32];
    }
    #pragma unroll
    for (int ii = 0; ii < 8; ii++) {
        size_t r = row0 + ty * 8 + ii;
        #pragma unroll
        for (int j = 0; j < 4; j++) {
            float2 p = unpack2(acc[ii][j]);
            p.x += bv[j].x; p.y += bv[j].y;
            *(float2*)&C[r * 128 + tx * 2 + j * 32] = p;
        }
    }
}

// ---------------- diff-weight precompute ----------------
__global__ __launch_bounds__(256)
void diff_kernel(const float* __restrict__ Wc1, const float* __restrict__ Wc2,
                 float* __restrict__ D1, float* __restrict__ D2)
{
    int i = blockIdx.x * 256 + threadIdx.x;
    D1[i] = Wc1[i] - Wc1[i + 16384];
    D2[i] = Wc2[i] - Wc2[i + 16384];
}

// =====================================================================
// trk node kernel (unchanged from R13)
// =====================================================================
__global__ __launch_bounds__(256, 2)
void trk_kernel(const float* __restrict__ X,
                const float* __restrict__ W1, const float* __restrict__ b1,
                const float* __restrict__ W2, const float* __restrict__ b2,
                const float* __restrict__ Wd2,
                float* __restrict__ Yf, float* __restrict__ Yu2)
{
    extern __shared__ float sm[];
    float* Hs  = sm;                    // 128*132 = 16896
    float* Wb  = Hs + 16896;            // 2*4096
    float* Xin = Wb + 8192;             // 128*8
    float* W1s = Xin + 1024;            // 8*128
    float* b1s = W1s + 1024;            // 128
    const int tid = threadIdx.x;
    const int tx = tid & 15, ty = tid >> 4;
    const size_t row0 = (size_t)blockIdx.x * 128;

    for (int t = tid; t < 1024; t += 256) Xin[t] = X[row0 * 8 + t];
    for (int t = tid; t < 1024; t += 256) W1s[t] = W1[t];
    if (tid < 128) b1s[tid] = b1[tid];
    __syncthreads();

    {
        int r = tid >> 1, ch = (tid & 1) * 64;
        float xr[8];
        #pragma unroll
        for (int d = 0; d < 8; d++) xr[d] = Xin[r * 8 + d];
        #pragma unroll 4
        for (int cc = 0; cc < 64; cc++) {
            int c = ch + cc;
            float a = b1s[c];
            #pragma unroll
            for (int d = 0; d < 8; d++) a = fmaf(xr[d], W1s[d * 128 + c], a);
            Hs[c * 132 + r] = eluf(a);
        }
    }

    u64 acc[8][4];
    zero_acc8(acc);
    gemm_pass(Hs, Wb, W2, acc, tid, tx, ty);

    {
        float2 bv[4];
        #pragma unroll
        for (int j = 0; j < 4; j++) bv[j] = *(const float2*)&b2[tx * 2 + j * 32];
        #pragma unroll
        for (int ii = 0; ii < 8; ii++) {
            int rr = ty * 8 + ii;
            #pragma unroll
            for (int j = 0; j < 4; j++) {
                float2 p = unpack2(acc[ii][j]);
                float va = fmaxf(p.x + bv[j].x, 0.f);
                float vb = fmaxf(p.y + bv[j].y, 0.f);
                int c = tx * 2 + j * 32;
                float2 o = {va, vb};
                *(float2*)&Yf[(row0 + rr) * 128 + c] = o;
                Hs[c * 132 + rr]       = va;
                Hs[(c + 1) * 132 + rr] = vb;
            }
        }
    }
    __syncthreads();

    zero_acc8(acc);
    gemm_pass(Hs, Wb, Wd2, acc, tid, tx, ty);
    store256(acc, Yu2, row0, tx, ty, nullptr);
}

// =====================================================================
// conv1 (fused sv MLP + V1 + U1), pad 132, float4-vectorized k loops.
// Score buffer aliases weight-chunk buffer (disjoint lifetimes).
// 256 threads/graph, ~70KB smem -> 3 blocks/SM.
// =====================================================================
__global__ __launch_bounds__(256, 3)
void conv1_fused(const float* __restrict__ trkF, const float* __restrict__ x_sv,
                 const float* __restrict__ Wsv1, const float* __restrict__ bsv1,
                 const float* __restrict__ Wsv2, const float* __restrict__ bsv2,
                 const float* __restrict__ Wd1,  const float* __restrict__ bc1g,
                 const float* __restrict__ Wbot1,
                 float* __restrict__ f1out)
{
    extern __shared__ float sm[];
    float* dsh  = sm;                  // 64*132 = 8448 trk
    float* ssh  = dsh + 8448;          // 16*132 = 2112 sv feats
    float* vsh  = ssh + 2112;          // 2112 hidden, then V1
    float* Wbuf = vsh + 2112;          // 4096 weight chunk
    float* sc   = Wbuf;                // ALIAS: scores live between svL2 and U1
    float* sn2  = Wbuf + 4096;         // 16
    float* S    = sn2 + 16;            // 672 smalls
    int*  idxs  = (int*)(S + 672);     // 512 ints

    float* xsv = S;          // 32
    float* w1  = S + 32;     // 256
    float* b1  = S + 288;    // 128
    float* b2  = S + 416;    // 128
    float* bc1 = S + 544;    // 128

    const int tid = threadIdx.x;
    const int tx = tid & 15, ty = tid >> 4;       // ty: 0..15
    const int lane = tid & 31, wid = tid >> 5;
    const int g = blockIdx.x;
    const float* dg = trkF + (size_t)g * 64 * 128;

    for (int t = tid; t < 64 * 128; t += 256)
        dsh[(t >> 7) * 132 + (t & 127)] = dg[t];
    if (tid < 32) xsv[tid] = x_sv[g * 32 + tid];
    w1[tid] = Wsv1[tid];
    if (tid < 128) { b1[tid] = bsv1[tid]; b2[tid] = bsv2[tid]; bc1[tid] = bc1g[tid]; }
    __syncthreads();

    // sv layer1 -> vsh (16 x 128, ld 132)
    {
        float x0 = xsv[ty * 2], x1 = xsv[ty * 2 + 1];
        #pragma unroll
        for (int j = 0; j < 4; j++) {
            int c = 2 * tx + 32 * j;
            vsh[ty * 132 + c]     = eluf(b1[c]     + x0 * w1[c]     + x1 * w1[128 + c]);
            vsh[ty * 132 + c + 1] = eluf(b1[c + 1] + x0 * w1[c + 1] + x1 * w1[128 + c + 1]);
        }
    }
    __syncthreads();

    // sv layer2 (streamed Wsv2) -> ssh = relu(...)
    {
        u64 a[4] = {0ull, 0ull, 0ull, 0ull};
        for (int kc = 0; kc < 4; kc++) {
            stage_chunk(Wbuf, Wsv2, kc, tid);
            __syncthreads();
            #pragma unroll 2
            for (int k4 = 0; k4 < 32; k4 += 4) {
                float4 sv4 = *(const float4*)&vsh[ty * 132 + kc * 32 + k4];
                #pragma unroll
                for (int q = 0; q < 4; q++) {
                    float el = (q == 0) ? sv4.x : (q == 1) ? sv4.y : (q == 2) ? sv4.z : sv4.w;
                    u64 s = splat2(el);
                    const u64* br = (const u64*)&Wbuf[(k4 + q) * 128];
                    ffma2(a[0], s, br[tx]);      ffma2(a[1], s, br[tx + 16]);
                    ffma2(a[2], s, br[tx + 32]); ffma2(a[3], s, br[tx + 48]);
                }
            }
            __syncthreads();
        }
        #pragma unroll
        for (int j = 0; j < 4; j++) {
            float2 p = unpack2(a[j]);
            int c = 2 * tx + 32 * j;
            ssh[ty * 132 + c]     = fmaxf(p.x + b2[c],     0.f);
            ssh[ty * 132 + c + 1] = fmaxf(p.y + b2[c + 1], 0.f);
        }
    }
    __syncthreads();

    // sv squared norms
    #pragma unroll
    for (int q = 0; q < 2; q++) {
        int row = wid * 2 + q;
        const float* rp = &ssh[row * 132];
        float e0 = rp[lane], e1 = rp[32 + lane], e2 = rp[64 + lane], e3 = rp[96 + lane];
        float s = e0*e0 + e1*e1 + e2*e2 + e3*e3;
        #pragma unroll
        for (int off = 16; off > 0; off >>= 1) s += __shfl_xor_sync(~0u, s, off);
        if (lane == 0) sn2[row] = s;
    }
    __syncthreads();

    // scores (float4-vectorized): i = tid>>2, jj = tid&3 -> j = jj + 4m
    {
        int i = tid >> 2, jj = tid & 3;
        u64 a[4] = {0ull, 0ull, 0ull, 0ull};
        #pragma unroll 4
        for (int k4 = 0; k4 < 128; k4 += 4) {
            float4 av = *(const float4*)&dsh[i * 132 + k4];
            u64 a01 = pack2f(av.x, av.y), a23 = pack2f(av.z, av.w);
            #pragma unroll
            for (int m = 0; m < 4; m++) {
                float4 bv = *(const float4*)&ssh[(jj + 4 * m) * 132 + k4];
                ffma2(a[m], a01, pack2f(bv.x, bv.y));
                ffma2(a[m], a23, pack2f(bv.z, bv.w));
            }
        }
        #pragma unroll
        for (int m = 0; m < 4; m++) {
            float2 p = unpack2(a[m]);
            int j = jj + 4 * m;
            sc[i * 17 + j] = sn2[j] - 2.f * (p.x + p.y);
        }
    }
    __syncthreads();

    // warp-parallel top-8 (tie -> lowest index)
    #pragma unroll
    for (int q = 0; q < 8; q++) {
        int row = wid * 8 + q;
        float mv = (lane < 16) ? sc[row * 17 + lane] : FLT_MAX;
        #pragma unroll
        for (int n = 0; n < KNN; n++) {
            float cv = mv; int ci = lane;
            #pragma unroll
            for (int off = 16; off > 0; off >>= 1) {
                float ov = __shfl_xor_sync(~0u, cv, off);
                int   oi = __shfl_xor_sync(~0u, ci, off);
                if (ov < cv || (ov == cv && oi < ci)) { cv = ov; ci = oi; }
            }
            if (lane == 0) idxs[row * 8 + n] = ci;
            if (lane == ci) mv = FLT_MAX;
        }
    }
    __syncthreads();   // scores dead -> Wbuf reusable

    // U1 = trk @ Wd1 -> registers (rows ty*4+ii, cols 2tx+32j)
    u64 accU[4][4];
    #pragma unroll
    for (int i = 0; i < 4; i++) { accU[i][0]=0; accU[i][1]=0; accU[i][2]=0; accU[i][3]=0; }
    for (int kc = 0; kc < 4; kc++) {
        stage_chunk(Wbuf, Wd1, kc, tid);
        __syncthreads();
        #pragma unroll 2
        for (int k4 = 0; k4 < 32; k4 += 4) {
            float4 arow[4];
            #pragma unroll
            for (int ii = 0; ii < 4; ii++)
                arow[ii] = *(const float4*)&dsh[(ty * 4 + ii) * 132 + kc * 32 + k4];
            #pragma unroll
            for (int q = 0; q < 4; q++) {
                const u64* br = (const u64*)&Wbuf[(k4 + q) * 128];
                u64 b0 = br[tx], b1v = br[tx + 16], b2v = br[tx + 32], b3v = br[tx + 48];
                #pragma unroll
                for (int ii = 0; ii < 4; ii++) {
                    float el = (q == 0) ? arow[ii].x : (q == 1) ? arow[ii].y
                             : (q == 2) ? arow[ii].z : arow[ii].w;
                    u64 s = splat2(el);
                    ffma2(accU[ii][0], s, b0);  ffma2(accU[ii][1], s, b1v);
                    ffma2(accU[ii][2], s, b2v); ffma2(accU[ii][3], s, b3v);
                }
            }
        }
        __syncthreads();
    }

    // V1 = svfeat @ Wbot1 -> vsh
    {
        u64 a[4] = {0ull, 0ull, 0ull, 0ull};
        for (int kc = 0; kc < 4; kc++) {
            stage_chunk(Wbuf, Wbot1, kc, tid);
            __syncthreads();
            #pragma unroll 2
            for (int k4 = 0; k4 < 32; k4 += 4) {
                float4 sv4 = *(const float4*)&ssh[ty * 132 + kc * 32 + k4];
                #pragma unroll
                for (int q = 0; q < 4; q++) {
                    float el = (q == 0) ? sv4.x : (q == 1) ? sv4.y : (q == 2) ? sv4.z : sv4.w;
                    u64 s = splat2(el);
                    const u64* br = (const u64*)&Wbuf[(k4 + q) * 128];
                    ffma2(a[0], s, br[tx]);      ffma2(a[1], s, br[tx + 16]);
                    ffma2(a[2], s, br[tx + 32]); ffma2(a[3], s, br[tx + 48]);
                }
            }
            __syncthreads();
        }
        #pragma unroll
        for (int j = 0; j < 4; j++) {
            float2 p = unpack2(a[j]);
            *(float2*)&vsh[ty * 132 + 2 * tx + 32 * j] = p;
        }
    }
    __syncthreads();

    // combine: f1 = elu(U1 + bc1 + max_n V1[idx])
    #pragma unroll
    for (int ii = 0; ii < 4; ii++) {
        int row = ty * 4 + ii;
        const int* ip = &idxs[row * 8];
        #pragma unroll
        for (int j = 0; j < 4; j++) {
            int c = 2 * tx + 32 * j;
            float mx = -FLT_MAX, my = -FLT_MAX;
            #pragma unroll
            for (int n = 0; n < KNN; n++) {
                float2 v = *(const float2*)&vsh[ip[n] * 132 + c];
                mx = fmaxf(mx, v.x); my = fmaxf(my, v.y);
            }
            float2 p = unpack2(accU[ii][j]);
            float2 o = { eluf(p.x + bc1[c] + mx), eluf(p.y + bc1[c + 1] + my) };
            *(float2*)&f1out[((size_t)g * 64 + row) * 128 + c] = o;
        }
    }
}

// =====================================================================
// conv2 (fused V2) + head, pad 132, float4-vectorized k loops.
// 512 threads, 2 blocks/SM.
// =====================================================================
__global__ __launch_bounds__(512, 2)
void conv2_head_kernel(const float* __restrict__ trkF, const float* __restrict__ f1,
                       const float* __restrict__ U,    const float* __restrict__ Wbot2,
                       const float* __restrict__ bc2,
                       const float* __restrict__ Wo1, const float* __restrict__ bo1,
                       const float* __restrict__ Wo2, const float* __restrict__ bo2,
                       const float* __restrict__ Wo3, const float* __restrict__ bo3,
                       const float* __restrict__ Wo4, const float* __restrict__ bo4,
                       float* __restrict__ out, int out_size)
{
    extern __shared__ float sm[];
    float* dsh = sm;                    // 64*132 = 8448 (trk; later V2)
    float* ssh = dsh + 8448;            // 8448 (f1)
    float* sc  = ssh + 8448;            // 64*65 = 4160 (scores; later W chunk)
    float* sn2 = sc + 4160;             // 64
    float* colsum = sn2 + 64;           // 512
    float* pooled = colsum + 512;       // 128
    float* h1 = pooled + 128;           // 64
    float* h2 = h1 + 64;                // 32
    float* h3 = h2 + 32;                // 4
    int*  idxs = (int*)(h3 + 4);        // 64*8

    const int g   = blockIdx.x;
    const int tid = threadIdx.x;
    const int wid = tid >> 5, lane = tid & 31;
    const int tx  = tid & 15, ty = tid >> 4;   // ty: 0..31
    const float* dg = trkF + (size_t)g * 64 * 128;
    const float* sg = f1   + (size_t)g * 64 * 128;
    const float* Ug = U    + (size_t)g * 64 * 128;

    for (int t = tid; t < 64 * 128; t += 512) {
        int r = t >> 7, c = t & 127;
        dsh[r * 132 + c] = dg[t];
        ssh[r * 132 + c] = sg[t];
    }
    __syncthreads();

    // f1 squared norms
    #pragma unroll
    for (int q = 0; q < 4; q++) {
        int row = wid * 4 + q;
        const float* rp = &ssh[row * 132];
        float e0 = rp[lane], e1 = rp[32 + lane], e2 = rp[64 + lane], e3 = rp[96 + lane];
        float s = e0*e0 + e1*e1 + e2*e2 + e3*e3;
        #pragma unroll
        for (int off = 16; off > 0; off >>= 1) s += __shfl_xor_sync(~0u, s, off);
        if (lane == 0) sn2[row] = s;
    }
    __syncthreads();

    // scores (float4-vectorized): rows 2ty,2ty+1; cols tx+16jj
    {
        u64 acc[2][4];
        #pragma unroll
        for (int a = 0; a < 2; a++)
            #pragma unroll
            for (int b = 0; b < 4; b++) acc[a][b] = 0ull;
        const int r0 = 2 * ty, r1 = 2 * ty + 1;
        #pragma unroll 4
        for (int k4 = 0; k4 < 128; k4 += 4) {
            float4 av0 = *(const float4*)&dsh[r0 * 132 + k4];
            float4 av1 = *(const float4*)&dsh[r1 * 132 + k4];
            u64 a0p = pack2f(av0.x, av0.y), a0q = pack2f(av0.z, av0.w);
            u64 a1p = pack2f(av1.x, av1.y), a1q = pack2f(av1.z, av1.w);
            #pragma unroll
            for (int jj = 0; jj < 4; jj++) {
                float4 bv = *(const float4*)&ssh[(tx + jj * 16) * 132 + k4];
                u64 bp = pack2f(bv.x, bv.y), bq = pack2f(bv.z, bv.w);
                ffma2(acc[0][jj], a0p, bp); ffma2(acc[0][jj], a0q, bq);
                ffma2(acc[1][jj], a1p, bp); ffma2(acc[1][jj], a1q, bq);
            }
        }
        #pragma unroll
        for (int ii = 0; ii < 2; ii++)
            #pragma unroll
            for (int jj = 0; jj < 4; jj++) {
                float2 p = unpack2(acc[ii][jj]);
                int j = tx + jj * 16;
                sc[(ty * 2 + ii) * 65 + j] = sn2[j] - 2.f * (p.x + p.y);
            }
    }
    __syncthreads();

    // warp-parallel top-8 over 64 candidates (2 per lane)
    #pragma unroll
    for (int q = 0; q < 4; q++) {
        int row = wid * 4 + q;
        float v0 = sc[row * 65 + lane];
        float v1 = sc[row * 65 + 32 + lane];
        #pragma unroll
        for (int n = 0; n < KNN; n++) {
            float cv; int ci;
            if (v1 < v0) { cv = v1; ci = lane + 32; }
            else         { cv = v0; ci = lane; }
            #pragma unroll
            for (int off = 16; off > 0; off >>= 1) {
                float ov = __shfl_xor_sync(~0u, cv, off);
                int   oi = __shfl_xor_sync(~0u, ci, off);
                if (ov < cv || (ov == cv && oi < ci)) { cv = ov; ci = oi; }
            }
            if (lane == 0) idxs[row * 8 + n] = ci;
            if (ci == lane)           v0 = FLT_MAX;
            else if (ci == lane + 32) v1 = FLT_MAX;
        }
    }
    __syncthreads();   // topk done: sc free for W chunks; trk (dsh) dead

    // ---- V2 = f1 @ Wbot2, in-block (float4 A loads) ----
    {
        u64 accv[2][4];
        #pragma unroll
        for (int a = 0; a < 2; a++)
            #pragma unroll
            for (int b = 0; b < 4; b++) accv[a][b] = 0ull;
        const int r0 = 2 * ty, r1 = 2 * ty + 1;
        for (int kc = 0; kc < 4; kc++) {
            #pragma unroll
            for (int e = 0; e < 2; e++) {
                int i4 = tid + e * 512;
                ((float4*)sc)[i4] = ((const float4*)Wbot2)[kc * 1024 + i4];
            }
            __syncthreads();
            #pragma unroll 2
            for (int k4 = 0; k4 < 32; k4 += 4) {
                float4 s0v = *(const float4*)&ssh[r0 * 132 + kc * 32 + k4];
                float4 s1v = *(const float4*)&ssh[r1 * 132 + kc * 32 + k4];
                #pragma unroll
                for (int q = 0; q < 4; q++) {
                    float e0 = (q == 0) ? s0v.x : (q == 1) ? s0v.y : (q == 2) ? s0v.z : s0v.w;
                    float e1 = (q == 0) ? s1v.x : (q == 1) ? s1v.y : (q == 2) ? s1v.z : s1v.w;
                    u64 s0 = splat2(e0), s1 = splat2(e1);
                    const u64* br = (const u64*)&sc[(k4 + q) * 128];
                    u64 b0 = br[tx], b1 = br[tx + 16], b2 = br[tx + 32], b3 = br[tx + 48];
                    ffma2(accv[0][0],s0,b0); ffma2(accv[0][1],s0,b1); ffma2(accv[0][2],s0,b2); ffma2(accv[0][3],s0,b3);
                    ffma2(accv[1][0],s1,b0); ffma2(accv[1][1],s1,b1); ffma2(accv[1][2],s1,b2); ffma2(accv[1][3],s1,b3);
                }
            }
            __syncthreads();
        }
        #pragma unroll
        for (int ii = 0; ii < 2; ii++) {
            int r = 2 * ty + ii;
            #pragma unroll
            for (int j = 0; j < 4; j++) {
                float2 p = unpack2(accv[ii][j]);
                *(float2*)&dsh[r * 132 + 2 * tx + 32 * j] = p;
            }
        }
    }
    __syncthreads();

    // combine: elu(U + bc2 + max_n V2[idx]) + column sums
    {
        int c = tid & 127, ih = tid >> 7;
        float bc = bc2[c];
        float csum = 0.f;
        #pragma unroll 4
        for (int i0 = 0; i0 < 64; i0 += 4) {
            int i = i0 + ih;
            const int* ip = &idxs[i * 8];
            float vmax = -FLT_MAX;
            #pragma unroll
            for (int n = 0; n < KNN; n++) vmax = fmaxf(vmax, dsh[ip[n] * 132 + c]);
            csum += eluf(Ug[i * 128 + c] + bc + vmax);
        }
        colsum[ih * 128 + c] = csum;
    }
    __syncthreads();
    if (tid < 128)
        pooled[tid] = (colsum[tid] + colsum[128 + tid] + colsum[256 + tid] + colsum[384 + tid]) * (1.f / 64.f);
    __syncthreads();
    if (tid < 64) {
        float a = bo1[tid];
        #pragma unroll 8
        for (int d = 0; d < 128; d++) a += pooled[d] * Wo1[d * 64 + tid];
        h1[tid] = eluf(a);
    }
    __syncthreads();
    if (tid < 32) {
        float a = bo2[tid];
        #pragma unroll 8
        for (int d = 0; d < 64; d++) a += h1[d] * Wo2[d * 32 + tid];
        h2[tid] = eluf(a);
    }
    __syncthreads();
    if (tid < 4) {
        float a = bo3[tid];
        #pragma unroll
        for (int d = 0; d < 32; d++) a += h2[d] * Wo3[d * 4 + tid];
        h3[tid] = eluf(a);
    }
    __syncthreads();
    if (tid == 0) {
        float a = bo4[0];
        #pragma unroll
        for (int d = 0; d < 4; d++) a += h3[d] * Wo4[d];
        out[g] = a;
        if (out_size >= 2 * G) out[G + g] = (float)g;
    }
}

// ---------------- launch ----------------
extern "C" void kernel_launch(void* const* d_in, const int* in_sizes, int n_in,
                              void* d_out, int out_size)
{
    const float* x_sv   = (const float*)d_in[0];
    const float* x_trk  = (const float*)d_in[1];
    const float* W_sv1  = (const float*)d_in[2];
    const float* b_sv1  = (const float*)d_in[3];
    const float* W_sv2  = (const float*)d_in[4];
    const float* b_sv2  = (const float*)d_in[5];
    const float* W_trk1 = (const float*)d_in[6];
    const float* b_trk1 = (const float*)d_in[7];
    const float* W_trk2 = (const float*)d_in[8];
    const float* b_trk2 = (const float*)d_in[9];
    const float* W_c1   = (const float*)d_in[10];
    const float* b_c1   = (const float*)d_in[11];
    const float* W_c2   = (const float*)d_in[12];
    const float* b_c2   = (const float*)d_in[13];
    const float* W_o1   = (const float*)d_in[14];
    const float* b_o1   = (const float*)d_in[15];
    const float* W_o2   = (const float*)d_in[16];
    const float* b_o2   = (const float*)d_in[17];
    const float* W_o3   = (const float*)d_in[18];
    const float* b_o3   = (const float*)d_in[19];
    const float* W_o4   = (const float*)d_in[20];
    const float* b_o4   = (const float*)d_in[21];
    float* out = (float*)d_out;

    float *p_trk, *p_U2, *p_f1, *p_Wd1, *p_Wd2;
    cudaGetSymbolAddress((void**)&p_trk, g_trk);
    cudaGetSymbolAddress((void**)&p_U2,  g_U2);
    cudaGetSymbolAddress((void**)&p_f1,  g_f1);
    cudaGetSymbolAddress((void**)&p_Wd1, g_Wd1);
    cudaGetSymbolAddress((void**)&p_Wd2, g_Wd2);

    const int smem_b  = (16896 + 8192 + 1024 + 1024 + 128) * 4;
    const int smem_c1 = (8448 + 2112 + 2112 + 4096 + 16 + 672) * 4 + 512 * 4;
    const int smem_d  = (8448 + 8448 + 4160 + 64 + 512 + 128 + 64 + 32 + 4) * 4 + 512 * 4;

    (void)cudaFuncSetAttribute(trk_kernel,        cudaFuncAttributeMaxDynamicSharedMemorySize, smem_b);
    (void)cudaFuncSetAttribute(conv1_fused,       cudaFuncAttributeMaxDynamicSharedMemorySize, smem_c1);
    (void)cudaFuncSetAttribute(conv2_head_kernel, cudaFuncAttributeMaxDynamicSharedMemorySize, smem_d);

    // 0: diff weights
    diff_kernel<<<64, 256>>>(W_c1, W_c2, p_Wd1, p_Wd2);

    // B: trk MLP + U2 (no bias; bc2 added in conv2)
    trk_kernel<<<G * NTRK / 128, 256, smem_b>>>(
        x_trk, W_trk1, b_trk1, W_trk2, b_trk2, p_Wd2, p_trk, p_U2);

    // C: conv1 fully fused -> f1
    conv1_fused<<<G, 256, smem_c1>>>(
        p_trk, x_sv, W_sv1, b_sv1, W_sv2, b_sv2,
        p_Wd1, b_c1, W_c1 + 16384, p_f1);

    // D: conv2 (+ fused V2) + head
    conv2_head_kernel<<<G, 512, smem_d>>>(p_trk, p_f1, p_U2,
        W_c2 + 16384, b_c2,
        W_o1, b_o1, W_o2, b_o2, W_o3, b_o3, W_o4, b_o4, out, out_size);
}